// round 2
// baseline (speedup 1.0000x reference)
#include <cuda_runtime.h>
#include <math.h>

#define C_DIM 1024
#define NSTR 4
#define HID 4096
#define NDC 24            // n*n + 2n
#define T_MAX 8192

// ---------------- scratch (static device globals; no allocations) -------------
__device__ float g_Weff[C_DIM * NDC];
__device__ float g_spre[T_MAX];
__device__ float g_hpost[T_MAX * NSTR];
__device__ float g_rsum[T_MAX * NSTR];
__device__ float g_premix[(size_t)T_MAX * C_DIM];
__device__ float g_h[(size_t)T_MAX * HID];
__device__ float g_fout[(size_t)T_MAX * C_DIM];
__device__ float g_merged[(size_t)T_MAX * HID];

// ---------------- Weff precompute: Weff[c][j] = sum_s rmsw[s*C+c]*Wdyn[(s*C+c)*24+j]
__global__ void weff_kernel(const float* __restrict__ rmsw, const float* __restrict__ Wdyn) {
    int idx = blockIdx.x * blockDim.x + threadIdx.x;
    if (idx >= C_DIM * NDC) return;
    int c = idx / NDC, j = idx % NDC;
    float s = 0.f;
    #pragma unroll
    for (int st = 0; st < NSTR; st++) {
        int k = st * C_DIM + c;
        s += rmsw[k] * Wdyn[(size_t)k * NDC + j];
    }
    g_Weff[idx] = s;
}

// ---------------- gates: rms, dynamic (24 dots), sigmoid gates, sinkhorn, premix
__global__ void gates_kernel(const float* __restrict__ x,
                             const float* __restrict__ bias_pre,
                             const float* __restrict__ bias_post,
                             const float* __restrict__ bias_res,
                             const float* __restrict__ alpha_pre,
                             const float* __restrict__ alpha_post,
                             const float* __restrict__ alpha_res) {
    int t = blockIdx.x;
    const float* xr = x + (size_t)t * C_DIM;
    int tid = threadIdx.x;                 // 256 threads

    float vals[25];
    #pragma unroll
    for (int j = 0; j < 25; j++) vals[j] = 0.f;

    for (int c = tid; c < C_DIM; c += 256) {
        float xv = xr[c];
        vals[24] += xv * xv;
        const float* w = &g_Weff[c * NDC];
        #pragma unroll
        for (int j = 0; j < NDC; j++) vals[j] += xv * w[j];
    }
    // warp reduce 25 values
    #pragma unroll
    for (int o = 16; o; o >>= 1) {
        #pragma unroll
        for (int j = 0; j < 25; j++)
            vals[j] += __shfl_down_sync(0xffffffffu, vals[j], o);
    }
    __shared__ float red[8][25];
    int wid = tid >> 5, lane = tid & 31;
    if (lane == 0) {
        #pragma unroll
        for (int j = 0; j < 25; j++) red[wid][j] = vals[j];
    }
    __syncthreads();
    __shared__ float sd[25];
    if (tid < 25) {
        float s = 0.f;
        #pragma unroll
        for (int w = 0; w < 8; w++) s += red[w][tid];
        sd[tid] = s;
    }
    __syncthreads();

    __shared__ float s_spre;
    if (tid == 0) {
        float rms = sqrtf(sd[24] * (1.f / (float)C_DIM) + 1e-8f);
        float inv = 1.f / rms;
        float dyn[NDC];
        #pragma unroll
        for (int j = 0; j < NDC; j++) dyn[j] = sd[j] * inv;

        float ap = alpha_pre[0], apo = alpha_post[0], ar = alpha_res[0];
        float spre = 0.f;
        #pragma unroll
        for (int s = 0; s < NSTR; s++)
            spre += 1.f / (1.f + expf(-(ap * dyn[s] + bias_pre[s])));
        float hp[NSTR];
        #pragma unroll
        for (int s = 0; s < NSTR; s++)
            hp[s] = 2.f / (1.f + expf(-(apo * dyn[NSTR + s] + bias_post[s])));

        float M[NSTR][NSTR];
        #pragma unroll
        for (int i = 0; i < NSTR; i++)
            #pragma unroll
            for (int j = 0; j < NSTR; j++)
                M[i][j] = expf(ar * dyn[2 * NSTR + i * NSTR + j] + bias_res[i * NSTR + j]);
        for (int it = 0; it < 20; it++) {
            float cs[NSTR];
            #pragma unroll
            for (int j = 0; j < NSTR; j++) {
                cs[j] = 0.f;
                #pragma unroll
                for (int i = 0; i < NSTR; i++) cs[j] += M[i][j];
                cs[j] = 1.f / (cs[j] + 1e-8f);
            }
            #pragma unroll
            for (int i = 0; i < NSTR; i++) {
                float rs = 0.f;
                #pragma unroll
                for (int j = 0; j < NSTR; j++) { M[i][j] *= cs[j]; rs += M[i][j]; }
                rs = 1.f / (rs + 1e-8f);
                #pragma unroll
                for (int j = 0; j < NSTR; j++) M[i][j] *= rs;
            }
        }
        g_spre[t] = spre;
        #pragma unroll
        for (int s = 0; s < NSTR; s++) {
            float rsum = 0.f;
            #pragma unroll
            for (int j = 0; j < NSTR; j++) rsum += M[s][j];
            g_hpost[t * NSTR + s] = hp[s];
            g_rsum[t * NSTR + s] = rsum;
        }
        s_spre = spre;
    }
    __syncthreads();
    float sp = s_spre;
    for (int c = tid; c < C_DIM; c += 256)
        g_premix[(size_t)t * C_DIM + c] = sp * xr[c];
}

// ---------------- merge: merged[t][s*C+c] = rsum[t,s]*x[t,c] + hpost[t,s]*fout[t,c]
__global__ void merge_kernel(const float* __restrict__ x, int T) {
    int total = T * HID / 4;
    for (int i = blockIdx.x * blockDim.x + threadIdx.x; i < total; i += gridDim.x * blockDim.x) {
        int e = i * 4;
        int t = e / HID;
        int r = e - t * HID;
        int s = r >> 10;
        int c = r & (C_DIM - 1);
        float rs = g_rsum[t * NSTR + s];
        float hp = g_hpost[t * NSTR + s];
        float4 xv = *(const float4*)&x[(size_t)t * C_DIM + c];
        float4 fv = *(const float4*)&g_fout[(size_t)t * C_DIM + c];
        float4 o;
        o.x = rs * xv.x + hp * fv.x;
        o.y = rs * xv.y + hp * fv.y;
        o.z = rs * xv.z + hp * fv.z;
        o.w = rs * xv.w + hp * fv.w;
        *(float4*)&g_merged[(size_t)e] = o;
    }
}

// ---------------- SGEMM: C = epi(A[MxK] @ B[KxN] + bias), EPI: 0=gelu 1=none 2=+resid
#define BM 128
#define BN 128
#define BK 8

__device__ __forceinline__ float gelu_exact(float v) {
    return 0.5f * v * (1.f + erff(v * 0.70710678118654752f));
}

template <int EPI>
__global__ void __launch_bounds__(256) sgemm_kernel(
    const float* __restrict__ A, const float* __restrict__ Bw,
    const float* __restrict__ bias, const float* __restrict__ resid,
    float* __restrict__ Cc, int M, int N, int K) {
    __shared__ float As[2][BK][BM];
    __shared__ float Bs[2][BK][BN];
    int tid = threadIdx.x;
    int bm = blockIdx.y * BM, bn = blockIdx.x * BN;

    int arow = tid >> 1, acol = (tid & 1) * 4;
    int brow = tid >> 5, bcol = (tid & 31) * 4;
    const float* Aptr = A + (size_t)(bm + arow) * K + acol;
    const float* Bptr = Bw + (size_t)brow * N + bn + bcol;

    float4 av = *(const float4*)Aptr;
    float4 bv = *(const float4*)Bptr;
    As[0][acol + 0][arow] = av.x;
    As[0][acol + 1][arow] = av.y;
    As[0][acol + 2][arow] = av.z;
    As[0][acol + 3][arow] = av.w;
    *(float4*)&Bs[0][brow][bcol] = bv;
    __syncthreads();

    float acc[8][8];
    #pragma unroll
    for (int i = 0; i < 8; i++)
        #pragma unroll
        for (int j = 0; j < 8; j++) acc[i][j] = 0.f;

    int tm = (tid >> 4) * 8, tn = (tid & 15) * 8;
    int KT = K / BK;
    int buf = 0;
    for (int kt = 0; kt < KT; kt++) {
        if (kt + 1 < KT) {
            av = *(const float4*)(Aptr + (kt + 1) * BK);
            bv = *(const float4*)(Bptr + (size_t)(kt + 1) * BK * N);
        }
        #pragma unroll
        for (int k = 0; k < BK; k++) {
            float4 a0 = *(float4*)&As[buf][k][tm];
            float4 a1 = *(float4*)&As[buf][k][tm + 4];
            float4 b0 = *(float4*)&Bs[buf][k][tn];
            float4 b1 = *(float4*)&Bs[buf][k][tn + 4];
            float a[8] = {a0.x, a0.y, a0.z, a0.w, a1.x, a1.y, a1.z, a1.w};
            float b[8] = {b0.x, b0.y, b0.z, b0.w, b1.x, b1.y, b1.z, b1.w};
            #pragma unroll
            for (int i = 0; i < 8; i++)
                #pragma unroll
                for (int j = 0; j < 8; j++) acc[i][j] = fmaf(a[i], b[j], acc[i][j]);
        }
        if (kt + 1 < KT) {
            As[buf ^ 1][acol + 0][arow] = av.x;
            As[buf ^ 1][acol + 1][arow] = av.y;
            As[buf ^ 1][acol + 2][arow] = av.z;
            As[buf ^ 1][acol + 3][arow] = av.w;
            *(float4*)&Bs[buf ^ 1][brow][bcol] = bv;
            __syncthreads();
            buf ^= 1;
        }
    }

    #pragma unroll
    for (int i = 0; i < 8; i++) {
        size_t row = (size_t)(bm + tm + i);
        float* crow = Cc + row * N + bn + tn;
        const float* rrow = (EPI == 2) ? (resid + row * N + bn + tn) : nullptr;
        #pragma unroll
        for (int jj = 0; jj < 8; jj += 4) {
            float4 v;
            float* vp = &v.x;
            #pragma unroll
            for (int q = 0; q < 4; q++) {
                float val = acc[i][jj + q] + bias[bn + tn + jj + q];
                if (EPI == 0) val = gelu_exact(val);
                if (EPI == 2) val += rrow[jj + q];
                vp[q] = val;
            }
            *(float4*)&crow[jj] = v;
        }
    }
}

// ---------------- launch ----------------
extern "C" void kernel_launch(void* const* d_in, const int* in_sizes, int n_in,
                              void* d_out, int out_size) {
    const float* x         = (const float*)d_in[0];
    const float* rms_w     = (const float*)d_in[1];
    const float* W_dyn     = (const float*)d_in[2];
    const float* bias_pre  = (const float*)d_in[3];
    const float* bias_post = (const float*)d_in[4];
    const float* bias_res  = (const float*)d_in[5];
    const float* alpha_pre = (const float*)d_in[6];
    const float* alpha_post= (const float*)d_in[7];
    const float* alpha_res = (const float*)d_in[8];
    const float* W1        = (const float*)d_in[9];
    const float* b1        = (const float*)d_in[10];
    const float* W2        = (const float*)d_in[11];
    const float* b2        = (const float*)d_in[12];
    const float* Wout      = (const float*)d_in[13];
    const float* bout      = (const float*)d_in[14];
    float* out = (float*)d_out;

    int T = in_sizes[0] / C_DIM;   // B*L tokens (8192)

    float *premix, *h, *fout, *merged;
    cudaGetSymbolAddress((void**)&premix, g_premix);
    cudaGetSymbolAddress((void**)&h, g_h);
    cudaGetSymbolAddress((void**)&fout, g_fout);
    cudaGetSymbolAddress((void**)&merged, g_merged);

    // 1. effective dynamic weights
    weff_kernel<<<(C_DIM * NDC + 255) / 256, 256>>>(rms_w, W_dyn);
    // 2. gates + sinkhorn + premix
    gates_kernel<<<T, 256>>>(x, bias_pre, bias_post, bias_res, alpha_pre, alpha_post, alpha_res);
    // 3. h = gelu(premix @ W1 + b1)   [T,1024]@[1024,4096]
    {
        dim3 grid(HID / BN, T / BM);
        sgemm_kernel<0><<<grid, 256>>>(premix, W1, b1, nullptr, h, T, HID, C_DIM);
    }
    // 4. fout = h @ W2 + b2           [T,4096]@[4096,1024]
    {
        dim3 grid(C_DIM / BN, T / BM);
        sgemm_kernel<1><<<grid, 256>>>(h, W2, b2, nullptr, fout, T, C_DIM, HID);
    }
    // 5. merged = rsum*x + hpost*fout  [T,4096]
    merge_kernel<<<1024, 256>>>(x, T);
    // 6. out = merged @ Wout + bout + x   [T,4096]@[4096,1024]
    {
        dim3 grid(C_DIM / BN, T / BM);
        sgemm_kernel<2><<<grid, 256>>>(merged, Wout, bout, x, out, T, C_DIM, HID);
    }
}

// round 3
// speedup vs baseline: 1.0008x; 1.0008x over previous
#include <cuda_runtime.h>
#include <math.h>

#define C_DIM 1024
#define NSTR 4
#define HID 4096
#define NDC 24            // n*n + 2n
#define T_MAX 8192

// ---------------- scratch (static device globals; no allocations) -------------
__device__ float g_Weff[C_DIM * NDC];
__device__ float g_spre[T_MAX];
__device__ float g_hpost[T_MAX * NSTR];
__device__ float g_rsum[T_MAX * NSTR];
__device__ float g_premix[(size_t)T_MAX * C_DIM];
__device__ float g_h[(size_t)T_MAX * HID];
__device__ float g_fout[(size_t)T_MAX * C_DIM];
__device__ float g_merged[(size_t)T_MAX * HID];

// ---------------- Weff precompute: Weff[c][j] = sum_s rmsw[s*C+c]*Wdyn[(s*C+c)*24+j]
__global__ void weff_kernel(const float* __restrict__ rmsw, const float* __restrict__ Wdyn) {
    int idx = blockIdx.x * blockDim.x + threadIdx.x;
    if (idx >= C_DIM * NDC) return;
    int c = idx / NDC, j = idx % NDC;
    float s = 0.f;
    #pragma unroll
    for (int st = 0; st < NSTR; st++) {
        int k = st * C_DIM + c;
        s += rmsw[k] * Wdyn[(size_t)k * NDC + j];
    }
    g_Weff[idx] = s;
}

// ---------------- gates: rms, dynamic (24 dots), sigmoid gates, sinkhorn, premix
__global__ void gates_kernel(const float* __restrict__ x,
                             const float* __restrict__ bias_pre,
                             const float* __restrict__ bias_post,
                             const float* __restrict__ bias_res,
                             const float* __restrict__ alpha_pre,
                             const float* __restrict__ alpha_post,
                             const float* __restrict__ alpha_res) {
    int t = blockIdx.x;
    const float* xr = x + (size_t)t * C_DIM;
    int tid = threadIdx.x;                 // 256 threads

    float vals[25];
    #pragma unroll
    for (int j = 0; j < 25; j++) vals[j] = 0.f;

    for (int c = tid; c < C_DIM; c += 256) {
        float xv = xr[c];
        vals[24] += xv * xv;
        const float* w = &g_Weff[c * NDC];
        #pragma unroll
        for (int j = 0; j < NDC; j++) vals[j] += xv * w[j];
    }
    // warp reduce 25 values
    #pragma unroll
    for (int o = 16; o; o >>= 1) {
        #pragma unroll
        for (int j = 0; j < 25; j++)
            vals[j] += __shfl_down_sync(0xffffffffu, vals[j], o);
    }
    __shared__ float red[8][25];
    int wid = tid >> 5, lane = tid & 31;
    if (lane == 0) {
        #pragma unroll
        for (int j = 0; j < 25; j++) red[wid][j] = vals[j];
    }
    __syncthreads();
    __shared__ float sd[25];
    if (tid < 25) {
        float s = 0.f;
        #pragma unroll
        for (int w = 0; w < 8; w++) s += red[w][tid];
        sd[tid] = s;
    }
    __syncthreads();

    __shared__ float s_spre;
    if (tid == 0) {
        float rms = sqrtf(sd[24] * (1.f / (float)C_DIM) + 1e-8f);
        float inv = 1.f / rms;
        float dyn[NDC];
        #pragma unroll
        for (int j = 0; j < NDC; j++) dyn[j] = sd[j] * inv;

        float ap = alpha_pre[0], apo = alpha_post[0], ar = alpha_res[0];
        float spre = 0.f;
        #pragma unroll
        for (int s = 0; s < NSTR; s++)
            spre += 1.f / (1.f + expf(-(ap * dyn[s] + bias_pre[s])));
        float hp[NSTR];
        #pragma unroll
        for (int s = 0; s < NSTR; s++)
            hp[s] = 2.f / (1.f + expf(-(apo * dyn[NSTR + s] + bias_post[s])));

        float M[NSTR][NSTR];
        #pragma unroll
        for (int i = 0; i < NSTR; i++)
            #pragma unroll
            for (int j = 0; j < NSTR; j++)
                M[i][j] = expf(ar * dyn[2 * NSTR + i * NSTR + j] + bias_res[i * NSTR + j]);
        for (int it = 0; it < 20; it++) {
            float cs[NSTR];
            #pragma unroll
            for (int j = 0; j < NSTR; j++) {
                cs[j] = 0.f;
                #pragma unroll
                for (int i = 0; i < NSTR; i++) cs[j] += M[i][j];
                cs[j] = 1.f / (cs[j] + 1e-8f);
            }
            #pragma unroll
            for (int i = 0; i < NSTR; i++) {
                float rs = 0.f;
                #pragma unroll
                for (int j = 0; j < NSTR; j++) { M[i][j] *= cs[j]; rs += M[i][j]; }
                rs = 1.f / (rs + 1e-8f);
                #pragma unroll
                for (int j = 0; j < NSTR; j++) M[i][j] *= rs;
            }
        }
        g_spre[t] = spre;
        #pragma unroll
        for (int s = 0; s < NSTR; s++) {
            float rsum = 0.f;
            #pragma unroll
            for (int j = 0; j < NSTR; j++) rsum += M[s][j];
            g_hpost[t * NSTR + s] = hp[s];
            g_rsum[t * NSTR + s] = rsum;
        }
        s_spre = spre;
    }
    __syncthreads();
    float sp = s_spre;
    for (int c = tid; c < C_DIM; c += 256)
        g_premix[(size_t)t * C_DIM + c] = sp * xr[c];
}

// ---------------- merge: merged[t][s*C+c] = rsum[t,s]*x[t,c] + hpost[t,s]*fout[t,c]
__global__ void merge_kernel(const float* __restrict__ x, int T) {
    int total = T * HID / 4;
    for (int i = blockIdx.x * blockDim.x + threadIdx.x; i < total; i += gridDim.x * blockDim.x) {
        int e = i * 4;
        int t = e / HID;
        int r = e - t * HID;
        int s = r >> 10;
        int c = r & (C_DIM - 1);
        float rs = g_rsum[t * NSTR + s];
        float hp = g_hpost[t * NSTR + s];
        float4 xv = *(const float4*)&x[(size_t)t * C_DIM + c];
        float4 fv = *(const float4*)&g_fout[(size_t)t * C_DIM + c];
        float4 o;
        o.x = rs * xv.x + hp * fv.x;
        o.y = rs * xv.y + hp * fv.y;
        o.z = rs * xv.z + hp * fv.z;
        o.w = rs * xv.w + hp * fv.w;
        *(float4*)&g_merged[(size_t)e] = o;
    }
}

// ---------------- SGEMM: C = epi(A[MxK] @ B[KxN] + bias), EPI: 0=gelu 1=none 2=+resid
#define BM 128
#define BN 128
#define BK 8

__device__ __forceinline__ float gelu_exact(float v) {
    return 0.5f * v * (1.f + erff(v * 0.70710678118654752f));
}

template <int EPI>
__global__ void __launch_bounds__(256) sgemm_kernel(
    const float* __restrict__ A, const float* __restrict__ Bw,
    const float* __restrict__ bias, const float* __restrict__ resid,
    float* __restrict__ Cc, int M, int N, int K) {
    __shared__ float As[2][BK][BM];
    __shared__ float Bs[2][BK][BN];
    int tid = threadIdx.x;
    int bm = blockIdx.y * BM, bn = blockIdx.x * BN;

    int arow = tid >> 1, acol = (tid & 1) * 4;
    int brow = tid >> 5, bcol = (tid & 31) * 4;
    const float* Aptr = A + (size_t)(bm + arow) * K + acol;
    const float* Bptr = Bw + (size_t)brow * N + bn + bcol;

    float4 av = *(const float4*)Aptr;
    float4 bv = *(const float4*)Bptr;
    As[0][acol + 0][arow] = av.x;
    As[0][acol + 1][arow] = av.y;
    As[0][acol + 2][arow] = av.z;
    As[0][acol + 3][arow] = av.w;
    *(float4*)&Bs[0][brow][bcol] = bv;
    __syncthreads();

    float acc[8][8];
    #pragma unroll
    for (int i = 0; i < 8; i++)
        #pragma unroll
        for (int j = 0; j < 8; j++) acc[i][j] = 0.f;

    int tm = (tid >> 4) * 8, tn = (tid & 15) * 8;
    int KT = K / BK;
    int buf = 0;
    for (int kt = 0; kt < KT; kt++) {
        if (kt + 1 < KT) {
            av = *(const float4*)(Aptr + (kt + 1) * BK);
            bv = *(const float4*)(Bptr + (size_t)(kt + 1) * BK * N);
        }
        #pragma unroll
        for (int k = 0; k < BK; k++) {
            float4 a0 = *(float4*)&As[buf][k][tm];
            float4 a1 = *(float4*)&As[buf][k][tm + 4];
            float4 b0 = *(float4*)&Bs[buf][k][tn];
            float4 b1 = *(float4*)&Bs[buf][k][tn + 4];
            float a[8] = {a0.x, a0.y, a0.z, a0.w, a1.x, a1.y, a1.z, a1.w};
            float b[8] = {b0.x, b0.y, b0.z, b0.w, b1.x, b1.y, b1.z, b1.w};
            #pragma unroll
            for (int i = 0; i < 8; i++)
                #pragma unroll
                for (int j = 0; j < 8; j++) acc[i][j] = fmaf(a[i], b[j], acc[i][j]);
        }
        if (kt + 1 < KT) {
            As[buf ^ 1][acol + 0][arow] = av.x;
            As[buf ^ 1][acol + 1][arow] = av.y;
            As[buf ^ 1][acol + 2][arow] = av.z;
            As[buf ^ 1][acol + 3][arow] = av.w;
            *(float4*)&Bs[buf ^ 1][brow][bcol] = bv;
            __syncthreads();
            buf ^= 1;
        }
    }

    #pragma unroll
    for (int i = 0; i < 8; i++) {
        size_t row = (size_t)(bm + tm + i);
        float* crow = Cc + row * N + bn + tn;
        const float* rrow = (EPI == 2) ? (resid + row * N + bn + tn) : nullptr;
        #pragma unroll
        for (int jj = 0; jj < 8; jj += 4) {
            float4 v;
            float* vp = &v.x;
            #pragma unroll
            for (int q = 0; q < 4; q++) {
                float val = acc[i][jj + q] + bias[bn + tn + jj + q];
                if (EPI == 0) val = gelu_exact(val);
                if (EPI == 2) val += rrow[jj + q];
                vp[q] = val;
            }
            *(float4*)&crow[jj] = v;
        }
    }
}

// ---------------- launch ----------------
extern "C" void kernel_launch(void* const* d_in, const int* in_sizes, int n_in,
                              void* d_out, int out_size) {
    const float* x         = (const float*)d_in[0];
    const float* rms_w     = (const float*)d_in[1];
    const float* W_dyn     = (const float*)d_in[2];
    const float* bias_pre  = (const float*)d_in[3];
    const float* bias_post = (const float*)d_in[4];
    const float* bias_res  = (const float*)d_in[5];
    const float* alpha_pre = (const float*)d_in[6];
    const float* alpha_post= (const float*)d_in[7];
    const float* alpha_res = (const float*)d_in[8];
    const float* W1        = (const float*)d_in[9];
    const float* b1        = (const float*)d_in[10];
    const float* W2        = (const float*)d_in[11];
    const float* b2        = (const float*)d_in[12];
    const float* Wout      = (const float*)d_in[13];
    const float* bout      = (const float*)d_in[14];
    float* out = (float*)d_out;

    int T = in_sizes[0] / C_DIM;   // B*L tokens (8192)

    float *premix, *h, *fout, *merged;
    cudaGetSymbolAddress((void**)&premix, g_premix);
    cudaGetSymbolAddress((void**)&h, g_h);
    cudaGetSymbolAddress((void**)&fout, g_fout);
    cudaGetSymbolAddress((void**)&merged, g_merged);

    // 1. effective dynamic weights
    weff_kernel<<<(C_DIM * NDC + 255) / 256, 256>>>(rms_w, W_dyn);
    // 2. gates + sinkhorn + premix
    gates_kernel<<<T, 256>>>(x, bias_pre, bias_post, bias_res, alpha_pre, alpha_post, alpha_res);
    // 3. h = gelu(premix @ W1 + b1)   [T,1024]@[1024,4096]
    {
        dim3 grid(HID / BN, T / BM);
        sgemm_kernel<0><<<grid, 256>>>(premix, W1, b1, nullptr, h, T, HID, C_DIM);
    }
    // 4. fout = h @ W2 + b2           [T,4096]@[4096,1024]
    {
        dim3 grid(C_DIM / BN, T / BM);
        sgemm_kernel<1><<<grid, 256>>>(h, W2, b2, nullptr, fout, T, C_DIM, HID);
    }
    // 5. merged = rsum*x + hpost*fout  [T,4096]
    merge_kernel<<<1024, 256>>>(x, T);
    // 6. out = merged @ Wout + bout + x   [T,4096]@[4096,1024]
    {
        dim3 grid(C_DIM / BN, T / BM);
        sgemm_kernel<2><<<grid, 256>>>(merged, Wout, bout, x, out, T, C_DIM, HID);
    }
}

// round 4
// speedup vs baseline: 2.2153x; 2.2136x over previous
#include <cuda_runtime.h>
#include <cuda_bf16.h>
#include <math.h>
#include <stdint.h>

#define C_DIM 1024
#define NSTR 4
#define HID 4096
#define NDC 24
#define T_MAX 8192

// ---------------- scratch ----------------
__device__ float g_Weff[C_DIM * NDC];
__device__ float g_hpost[T_MAX * NSTR];
__device__ float g_rsum[T_MAX * NSTR];
__device__ float g_fout[(size_t)T_MAX * C_DIM];

__device__ __nv_bfloat16 g_premixH[(size_t)T_MAX * C_DIM];
__device__ __nv_bfloat16 g_premixL[(size_t)T_MAX * C_DIM];
__device__ __nv_bfloat16 g_hH[(size_t)T_MAX * HID];
__device__ __nv_bfloat16 g_hL[(size_t)T_MAX * HID];
__device__ __nv_bfloat16 g_mergedH[(size_t)T_MAX * HID];
__device__ __nv_bfloat16 g_mergedL[(size_t)T_MAX * HID];
__device__ __nv_bfloat16 g_W1H[(size_t)C_DIM * HID];
__device__ __nv_bfloat16 g_W1L[(size_t)C_DIM * HID];
__device__ __nv_bfloat16 g_W2H[(size_t)HID * C_DIM];
__device__ __nv_bfloat16 g_W2L[(size_t)HID * C_DIM];
__device__ __nv_bfloat16 g_WoH[(size_t)HID * C_DIM];
__device__ __nv_bfloat16 g_WoL[(size_t)HID * C_DIM];

// ---------------- helpers ----------------
__device__ __forceinline__ uint32_t sa(const void* p) {
    return (uint32_t)__cvta_generic_to_shared(p);
}
__device__ __forceinline__ void ldsm4(uint32_t* r, uint32_t addr) {
    asm volatile("ldmatrix.sync.aligned.m8n8.x4.shared.b16 {%0,%1,%2,%3},[%4];"
                 : "=r"(r[0]), "=r"(r[1]), "=r"(r[2]), "=r"(r[3]) : "r"(addr));
}
__device__ __forceinline__ void ldsm4t(uint32_t* r, uint32_t addr) {
    asm volatile("ldmatrix.sync.aligned.m8n8.x4.trans.shared.b16 {%0,%1,%2,%3},[%4];"
                 : "=r"(r[0]), "=r"(r[1]), "=r"(r[2]), "=r"(r[3]) : "r"(addr));
}
__device__ __forceinline__ void mma_bf16(float* c, const uint32_t* a, const uint32_t* b) {
    asm volatile(
        "mma.sync.aligned.m16n8k16.row.col.f32.bf16.bf16.f32 "
        "{%0,%1,%2,%3},{%4,%5,%6,%7},{%8,%9},{%0,%1,%2,%3};"
        : "+f"(c[0]), "+f"(c[1]), "+f"(c[2]), "+f"(c[3])
        : "r"(a[0]), "r"(a[1]), "r"(a[2]), "r"(a[3]), "r"(b[0]), "r"(b[1]));
}
__device__ __forceinline__ float gelu_exact(float v) {
    return 0.5f * v * (1.f + erff(v * 0.70710678118654752f));
}
__device__ __forceinline__ void split_bf(float v, __nv_bfloat16& h, __nv_bfloat16& l) {
    h = __float2bfloat16(v);
    l = __float2bfloat16(v - __bfloat162float(h));
}

// ---------------- Weff precompute ----------------
__global__ void weff_kernel(const float* __restrict__ rmsw, const float* __restrict__ Wdyn) {
    int idx = blockIdx.x * blockDim.x + threadIdx.x;
    if (idx >= C_DIM * NDC) return;
    int c = idx / NDC, j = idx % NDC;
    float s = 0.f;
    #pragma unroll
    for (int st = 0; st < NSTR; st++) {
        int k = st * C_DIM + c;
        s += rmsw[k] * Wdyn[(size_t)k * NDC + j];
    }
    g_Weff[idx] = s;
}

// ---------------- weight split (fp32 -> hi/lo bf16) ----------------
__global__ void split_kernel(const float* __restrict__ W, __nv_bfloat16* __restrict__ H,
                             __nv_bfloat16* __restrict__ L, int n4) {
    for (int i = blockIdx.x * blockDim.x + threadIdx.x; i < n4; i += gridDim.x * blockDim.x) {
        float4 v = *(const float4*)&W[(size_t)i * 4];
        __nv_bfloat16 h0, h1, h2, h3, l0, l1, l2, l3;
        split_bf(v.x, h0, l0); split_bf(v.y, h1, l1);
        split_bf(v.z, h2, l2); split_bf(v.w, h3, l3);
        __nv_bfloat162 hh0; hh0.x = h0; hh0.y = h1;
        __nv_bfloat162 hh1; hh1.x = h2; hh1.y = h3;
        __nv_bfloat162 ll0; ll0.x = l0; ll0.y = l1;
        __nv_bfloat162 ll1; ll1.x = l2; ll1.y = l3;
        *(__nv_bfloat162*)&H[(size_t)i * 4]     = hh0;
        *(__nv_bfloat162*)&H[(size_t)i * 4 + 2] = hh1;
        *(__nv_bfloat162*)&L[(size_t)i * 4]     = ll0;
        *(__nv_bfloat162*)&L[(size_t)i * 4 + 2] = ll1;
    }
}

// ---------------- gates: rms, dyn, sigmoid, sinkhorn, premix(hi/lo) ----------------
__global__ void gates_kernel(const float* __restrict__ x,
                             const float* __restrict__ bias_pre,
                             const float* __restrict__ bias_post,
                             const float* __restrict__ bias_res,
                             const float* __restrict__ alpha_pre,
                             const float* __restrict__ alpha_post,
                             const float* __restrict__ alpha_res) {
    int t = blockIdx.x;
    const float* xr = x + (size_t)t * C_DIM;
    int tid = threadIdx.x;

    float vals[25];
    #pragma unroll
    for (int j = 0; j < 25; j++) vals[j] = 0.f;

    for (int c = tid; c < C_DIM; c += 256) {
        float xv = xr[c];
        vals[24] += xv * xv;
        const float* w = &g_Weff[c * NDC];
        #pragma unroll
        for (int j = 0; j < NDC; j++) vals[j] += xv * w[j];
    }
    #pragma unroll
    for (int o = 16; o; o >>= 1)
        #pragma unroll
        for (int j = 0; j < 25; j++)
            vals[j] += __shfl_down_sync(0xffffffffu, vals[j], o);
    __shared__ float red[8][25];
    int wid = tid >> 5, lane = tid & 31;
    if (lane == 0)
        #pragma unroll
        for (int j = 0; j < 25; j++) red[wid][j] = vals[j];
    __syncthreads();
    __shared__ float sd[25];
    if (tid < 25) {
        float s = 0.f;
        #pragma unroll
        for (int w = 0; w < 8; w++) s += red[w][tid];
        sd[tid] = s;
    }
    __syncthreads();

    __shared__ float s_spre;
    if (tid == 0) {
        float rms = sqrtf(sd[24] * (1.f / (float)C_DIM) + 1e-8f);
        float inv = 1.f / rms;
        float dyn[NDC];
        #pragma unroll
        for (int j = 0; j < NDC; j++) dyn[j] = sd[j] * inv;

        float ap = alpha_pre[0], apo = alpha_post[0], ar = alpha_res[0];
        float spre = 0.f;
        #pragma unroll
        for (int s = 0; s < NSTR; s++)
            spre += 1.f / (1.f + expf(-(ap * dyn[s] + bias_pre[s])));
        float hp[NSTR];
        #pragma unroll
        for (int s = 0; s < NSTR; s++)
            hp[s] = 2.f / (1.f + expf(-(apo * dyn[NSTR + s] + bias_post[s])));

        float M[NSTR][NSTR];
        #pragma unroll
        for (int i = 0; i < NSTR; i++)
            #pragma unroll
            for (int j = 0; j < NSTR; j++)
                M[i][j] = expf(ar * dyn[2 * NSTR + i * NSTR + j] + bias_res[i * NSTR + j]);
        for (int it = 0; it < 20; it++) {
            float cs[NSTR];
            #pragma unroll
            for (int j = 0; j < NSTR; j++) {
                cs[j] = 0.f;
                #pragma unroll
                for (int i = 0; i < NSTR; i++) cs[j] += M[i][j];
                cs[j] = 1.f / (cs[j] + 1e-8f);
            }
            #pragma unroll
            for (int i = 0; i < NSTR; i++) {
                float rs = 0.f;
                #pragma unroll
                for (int j = 0; j < NSTR; j++) { M[i][j] *= cs[j]; rs += M[i][j]; }
                rs = 1.f / (rs + 1e-8f);
                #pragma unroll
                for (int j = 0; j < NSTR; j++) M[i][j] *= rs;
            }
        }
        #pragma unroll
        for (int s = 0; s < NSTR; s++) {
            float rsum = 0.f;
            #pragma unroll
            for (int j = 0; j < NSTR; j++) rsum += M[s][j];
            g_hpost[t * NSTR + s] = hp[s];
            g_rsum[t * NSTR + s] = rsum;
        }
        s_spre = spre;
    }
    __syncthreads();
    float sp = s_spre;
    for (int c = tid; c < C_DIM; c += 256) {
        float v = sp * xr[c];
        __nv_bfloat16 h, l;
        split_bf(v, h, l);
        g_premixH[(size_t)t * C_DIM + c] = h;
        g_premixL[(size_t)t * C_DIM + c] = l;
    }
}

// ---------------- merge: merged = rsum*x + hpost*fout, write hi/lo ----------------
__global__ void merge_kernel(const float* __restrict__ x, int T) {
    int total = T * HID / 4;
    for (int i = blockIdx.x * blockDim.x + threadIdx.x; i < total; i += gridDim.x * blockDim.x) {
        int e = i * 4;
        int t = e / HID;
        int r = e - t * HID;
        int s = r >> 10;
        int c = r & (C_DIM - 1);
        float rs = g_rsum[t * NSTR + s];
        float hp = g_hpost[t * NSTR + s];
        float4 xv = *(const float4*)&x[(size_t)t * C_DIM + c];
        float4 fv = *(const float4*)&g_fout[(size_t)t * C_DIM + c];
        float o0 = rs * xv.x + hp * fv.x;
        float o1 = rs * xv.y + hp * fv.y;
        float o2 = rs * xv.z + hp * fv.z;
        float o3 = rs * xv.w + hp * fv.w;
        __nv_bfloat16 h0, h1, h2, h3, l0, l1, l2, l3;
        split_bf(o0, h0, l0); split_bf(o1, h1, l1);
        split_bf(o2, h2, l2); split_bf(o3, h3, l3);
        __nv_bfloat162 p;
        p.x = h0; p.y = h1; *(__nv_bfloat162*)&g_mergedH[(size_t)e] = p;
        p.x = h2; p.y = h3; *(__nv_bfloat162*)&g_mergedH[(size_t)e + 2] = p;
        p.x = l0; p.y = l1; *(__nv_bfloat162*)&g_mergedL[(size_t)e] = p;
        p.x = l2; p.y = l3; *(__nv_bfloat162*)&g_mergedL[(size_t)e + 2] = p;
    }
}

// ---------------- bf16x3 tensor-core GEMM ----------------
// C[M,N] = epi(A @ B + bias);  A,B given as hi/lo bf16, row-major.
// EPI 0: gelu -> write hi/lo bf16 (CH/CL). EPI 1: write fp32. EPI 2: +resid, write fp32.
#define BM 128
#define BN 128
#define BK 16
#define APAD 24
#define BPAD 136

template <int EPI>
__global__ void __launch_bounds__(256) mma_gemm(
    const __nv_bfloat16* __restrict__ AH, const __nv_bfloat16* __restrict__ AL,
    const __nv_bfloat16* __restrict__ BH, const __nv_bfloat16* __restrict__ BL,
    const float* __restrict__ bias, const float* __restrict__ resid,
    float* __restrict__ Cf, __nv_bfloat16* __restrict__ CH, __nv_bfloat16* __restrict__ CL,
    int M, int N, int K) {
    __shared__ __nv_bfloat16 AsH[2][BM][APAD];
    __shared__ __nv_bfloat16 AsL[2][BM][APAD];
    __shared__ __nv_bfloat16 BsH[2][BK][BPAD];
    __shared__ __nv_bfloat16 BsL[2][BK][BPAD];

    int tid = threadIdx.x;
    int lane = tid & 31;
    int wid = tid >> 5;
    int wm = wid & 1;      // 2 warps along M (64 rows each)
    int wn = wid >> 1;     // 4 warps along N (32 cols each)
    int bm = blockIdx.y * BM, bn = blockIdx.x * BN;

    int arow = tid >> 1, acol8 = (tid & 1) * 8;
    int brow = tid >> 4, bcol8 = (tid & 15) * 8;
    const __nv_bfloat16* pAH = AH + (size_t)(bm + arow) * K + acol8;
    const __nv_bfloat16* pAL = AL + (size_t)(bm + arow) * K + acol8;
    const __nv_bfloat16* pBH = BH + (size_t)brow * N + bn + bcol8;
    const __nv_bfloat16* pBL = BL + (size_t)brow * N + bn + bcol8;

    uint4 vah = *(const uint4*)pAH;
    uint4 val_ = *(const uint4*)pAL;
    uint4 vbh = *(const uint4*)pBH;
    uint4 vbl = *(const uint4*)pBL;
    *(uint4*)&AsH[0][arow][acol8] = vah;
    *(uint4*)&AsL[0][arow][acol8] = val_;
    *(uint4*)&BsH[0][brow][bcol8] = vbh;
    *(uint4*)&BsL[0][brow][bcol8] = vbl;
    __syncthreads();

    float acc[4][4][4];
    #pragma unroll
    for (int i = 0; i < 4; i++)
        #pragma unroll
        for (int j = 0; j < 4; j++)
            #pragma unroll
            for (int q = 0; q < 4; q++) acc[i][j][q] = 0.f;

    int a_m = wm * 64 + (lane & 15);
    int a_k = (lane >> 4) * 8;
    int b_k = ((lane >> 3) & 1) * 8 + (lane & 7);
    int b_n0 = wn * 32 + (lane >> 4) * 8;

    int KT = K / BK;
    int buf = 0;
    for (int kt = 0; kt < KT; kt++) {
        if (kt + 1 < KT) {
            int k16 = (kt + 1) * BK;
            vah  = *(const uint4*)(pAH + k16);
            val_ = *(const uint4*)(pAL + k16);
            vbh  = *(const uint4*)(pBH + (size_t)k16 * N);
            vbl  = *(const uint4*)(pBL + (size_t)k16 * N);
        }

        uint32_t aH[4][4], aL[4][4], bH[4][2], bL[4][2];
        #pragma unroll
        for (int mt = 0; mt < 4; mt++) {
            ldsm4(aH[mt], sa(&AsH[buf][a_m + mt * 16][a_k]));
            ldsm4(aL[mt], sa(&AsL[buf][a_m + mt * 16][a_k]));
        }
        #pragma unroll
        for (int nr = 0; nr < 2; nr++) {
            uint32_t r[4];
            ldsm4t(r, sa(&BsH[buf][b_k][b_n0 + nr * 16]));
            bH[nr * 2][0] = r[0]; bH[nr * 2][1] = r[1];
            bH[nr * 2 + 1][0] = r[2]; bH[nr * 2 + 1][1] = r[3];
            ldsm4t(r, sa(&BsL[buf][b_k][b_n0 + nr * 16]));
            bL[nr * 2][0] = r[0]; bL[nr * 2][1] = r[1];
            bL[nr * 2 + 1][0] = r[2]; bL[nr * 2 + 1][1] = r[3];
        }

        #pragma unroll
        for (int mt = 0; mt < 4; mt++)
            #pragma unroll
            for (int nt = 0; nt < 4; nt++) {
                mma_bf16(acc[mt][nt], aH[mt], bH[nt]);
                mma_bf16(acc[mt][nt], aH[mt], bL[nt]);
                mma_bf16(acc[mt][nt], aL[mt], bH[nt]);
            }

        if (kt + 1 < KT) {
            *(uint4*)&AsH[buf ^ 1][arow][acol8] = vah;
            *(uint4*)&AsL[buf ^ 1][arow][acol8] = val_;
            *(uint4*)&BsH[buf ^ 1][brow][bcol8] = vbh;
            *(uint4*)&BsL[buf ^ 1][brow][bcol8] = vbl;
            __syncthreads();
            buf ^= 1;
        }
    }

    int g = lane >> 2, tg = lane & 3;
    #pragma unroll
    for (int mt = 0; mt < 4; mt++)
        #pragma unroll
        for (int nt = 0; nt < 4; nt++) {
            int row = bm + wm * 64 + mt * 16 + g;
            int col = bn + wn * 32 + nt * 8 + tg * 2;
            float b0 = bias[col], b1 = bias[col + 1];
            #pragma unroll
            for (int half = 0; half < 2; half++) {
                int r = row + half * 8;
                size_t off = (size_t)r * N + col;
                float v0 = acc[mt][nt][half * 2 + 0] + b0;
                float v1 = acc[mt][nt][half * 2 + 1] + b1;
                if (EPI == 0) {
                    v0 = gelu_exact(v0);
                    v1 = gelu_exact(v1);
                    __nv_bfloat16 h0, h1, l0, l1;
                    split_bf(v0, h0, l0);
                    split_bf(v1, h1, l1);
                    __nv_bfloat162 p;
                    p.x = h0; p.y = h1; *(__nv_bfloat162*)&CH[off] = p;
                    p.x = l0; p.y = l1; *(__nv_bfloat162*)&CL[off] = p;
                } else if (EPI == 1) {
                    float2 o; o.x = v0; o.y = v1;
                    *(float2*)&Cf[off] = o;
                } else {
                    float2 rr = *(const float2*)&resid[off];
                    float2 o; o.x = v0 + rr.x; o.y = v1 + rr.y;
                    *(float2*)&Cf[off] = o;
                }
            }
        }
}

// ---------------- launch ----------------
extern "C" void kernel_launch(void* const* d_in, const int* in_sizes, int n_in,
                              void* d_out, int out_size) {
    const float* x         = (const float*)d_in[0];
    const float* rms_w     = (const float*)d_in[1];
    const float* W_dyn     = (const float*)d_in[2];
    const float* bias_pre  = (const float*)d_in[3];
    const float* bias_post = (const float*)d_in[4];
    const float* bias_res  = (const float*)d_in[5];
    const float* alpha_pre = (const float*)d_in[6];
    const float* alpha_post= (const float*)d_in[7];
    const float* alpha_res = (const float*)d_in[8];
    const float* W1        = (const float*)d_in[9];
    const float* b1        = (const float*)d_in[10];
    const float* W2        = (const float*)d_in[11];
    const float* b2        = (const float*)d_in[12];
    const float* Wout      = (const float*)d_in[13];
    const float* bout      = (const float*)d_in[14];
    float* out = (float*)d_out;

    int T = in_sizes[0] / C_DIM;   // 8192

    __nv_bfloat16 *premixH, *premixL, *hH, *hL, *mergedH, *mergedL;
    __nv_bfloat16 *w1H, *w1L, *w2H, *w2L, *woH, *woL;
    float *fout;
    cudaGetSymbolAddress((void**)&premixH, g_premixH);
    cudaGetSymbolAddress((void**)&premixL, g_premixL);
    cudaGetSymbolAddress((void**)&hH, g_hH);
    cudaGetSymbolAddress((void**)&hL, g_hL);
    cudaGetSymbolAddress((void**)&mergedH, g_mergedH);
    cudaGetSymbolAddress((void**)&mergedL, g_mergedL);
    cudaGetSymbolAddress((void**)&w1H, g_W1H);
    cudaGetSymbolAddress((void**)&w1L, g_W1L);
    cudaGetSymbolAddress((void**)&w2H, g_W2H);
    cudaGetSymbolAddress((void**)&w2L, g_W2L);
    cudaGetSymbolAddress((void**)&woH, g_WoH);
    cudaGetSymbolAddress((void**)&woL, g_WoL);
    cudaGetSymbolAddress((void**)&fout, g_fout);

    // 1. effective dynamic weights + weight splits
    weff_kernel<<<(C_DIM * NDC + 255) / 256, 256>>>(rms_w, W_dyn);
    int wn4 = C_DIM * HID / 4;
    split_kernel<<<2048, 256>>>(W1, w1H, w1L, wn4);
    split_kernel<<<2048, 256>>>(W2, w2H, w2L, wn4);
    split_kernel<<<2048, 256>>>(Wout, woH, woL, wn4);
    // 2. gates + sinkhorn + premix (hi/lo)
    gates_kernel<<<T, 256>>>(x, bias_pre, bias_post, bias_res, alpha_pre, alpha_post, alpha_res);
    // 3. h = gelu(premix @ W1 + b1) -> hi/lo bf16
    {
        dim3 grid(HID / BN, T / BM);
        mma_gemm<0><<<grid, 256>>>(premixH, premixL, w1H, w1L, b1, nullptr,
                                   nullptr, hH, hL, T, HID, C_DIM);
    }
    // 4. fout = h @ W2 + b2  (fp32)
    {
        dim3 grid(C_DIM / BN, T / BM);
        mma_gemm<1><<<grid, 256>>>(hH, hL, w2H, w2L, b2, nullptr,
                                   fout, nullptr, nullptr, T, C_DIM, HID);
    }
    // 5. merged = rsum*x + hpost*fout -> hi/lo bf16
    merge_kernel<<<1024, 256>>>(x, T);
    // 6. out = merged @ Wout + bout + x  (fp32)
    {
        dim3 grid(C_DIM / BN, T / BM);
        mma_gemm<2><<<grid, 256>>>(mergedH, mergedL, woH, woL, bout, x,
                                   out, nullptr, nullptr, T, C_DIM, HID);
    }
}

// round 6
// speedup vs baseline: 2.6765x; 1.2082x over previous
#include <cuda_runtime.h>
#include <cuda_bf16.h>
#include <math.h>
#include <stdint.h>

#define C_DIM 1024
#define NSTR 4
#define HID 4096
#define NDC 24
#define T_MAX 8192

// ---------------- scratch ----------------
__device__ float g_Weff[C_DIM * NDC];
__device__ float g_hpost[T_MAX * NSTR];
__device__ float g_rsum[T_MAX * NSTR];

__device__ __nv_bfloat16 g_premixH[(size_t)T_MAX * C_DIM];
__device__ __nv_bfloat16 g_premixL[(size_t)T_MAX * C_DIM];
__device__ __nv_bfloat16 g_hH[(size_t)T_MAX * HID];
__device__ __nv_bfloat16 g_hL[(size_t)T_MAX * HID];
__device__ __nv_bfloat16 g_mergedH[(size_t)T_MAX * HID];
__device__ __nv_bfloat16 g_mergedL[(size_t)T_MAX * HID];
__device__ __nv_bfloat16 g_W1H[(size_t)C_DIM * HID];
__device__ __nv_bfloat16 g_W1L[(size_t)C_DIM * HID];
__device__ __nv_bfloat16 g_W2H[(size_t)HID * C_DIM];
__device__ __nv_bfloat16 g_W2L[(size_t)HID * C_DIM];
__device__ __nv_bfloat16 g_WoH[(size_t)HID * C_DIM];
__device__ __nv_bfloat16 g_WoL[(size_t)HID * C_DIM];

// ---------------- helpers ----------------
__device__ __forceinline__ uint32_t sa(const void* p) {
    return (uint32_t)__cvta_generic_to_shared(p);
}
__device__ __forceinline__ void ldsm4(uint32_t* r, uint32_t addr) {
    asm volatile("ldmatrix.sync.aligned.m8n8.x4.shared.b16 {%0,%1,%2,%3},[%4];"
                 : "=r"(r[0]), "=r"(r[1]), "=r"(r[2]), "=r"(r[3]) : "r"(addr));
}
__device__ __forceinline__ void ldsm4t(uint32_t* r, uint32_t addr) {
    asm volatile("ldmatrix.sync.aligned.m8n8.x4.trans.shared.b16 {%0,%1,%2,%3},[%4];"
                 : "=r"(r[0]), "=r"(r[1]), "=r"(r[2]), "=r"(r[3]) : "r"(addr));
}
__device__ __forceinline__ void mma_bf16(float* c, const uint32_t* a, const uint32_t* b) {
    asm volatile(
        "mma.sync.aligned.m16n8k16.row.col.f32.bf16.bf16.f32 "
        "{%0,%1,%2,%3},{%4,%5,%6,%7},{%8,%9},{%0,%1,%2,%3};"
        : "+f"(c[0]), "+f"(c[1]), "+f"(c[2]), "+f"(c[3])
        : "r"(a[0]), "r"(a[1]), "r"(a[2]), "r"(a[3]), "r"(b[0]), "r"(b[1]));
}
__device__ __forceinline__ float gelu_exact(float v) {
    return 0.5f * v * (1.f + erff(v * 0.70710678118654752f));
}
__device__ __forceinline__ void split_bf(float v, __nv_bfloat16& h, __nv_bfloat16& l) {
    h = __float2bfloat16(v);
    l = __float2bfloat16(v - __bfloat162float(h));
}
#define CP16(dst, src) \
    asm volatile("cp.async.cg.shared.global [%0], [%1], 16;" :: "r"(dst), "l"(src))
#define CP_COMMIT() asm volatile("cp.async.commit_group;" ::: "memory")
#define CP_WAIT2() asm volatile("cp.async.wait_group 2;" ::: "memory")

// ---------------- Weff precompute ----------------
__global__ void weff_kernel(const float* __restrict__ rmsw, const float* __restrict__ Wdyn) {
    int idx = blockIdx.x * blockDim.x + threadIdx.x;
    if (idx >= C_DIM * NDC) return;
    int c = idx / NDC, j = idx % NDC;
    float s = 0.f;
    #pragma unroll
    for (int st = 0; st < NSTR; st++) {
        int k = st * C_DIM + c;
        s += rmsw[k] * Wdyn[(size_t)k * NDC + j];
    }
    g_Weff[idx] = s;
}

// ---------------- weight split (fp32 -> hi/lo bf16, row-major kept) ----------------
__global__ void split_kernel(const float* __restrict__ W, __nv_bfloat16* __restrict__ H,
                             __nv_bfloat16* __restrict__ L, int n4) {
    for (int i = blockIdx.x * blockDim.x + threadIdx.x; i < n4; i += gridDim.x * blockDim.x) {
        float4 v = *(const float4*)&W[(size_t)i * 4];
        __nv_bfloat16 h0, h1, h2, h3, l0, l1, l2, l3;
        split_bf(v.x, h0, l0); split_bf(v.y, h1, l1);
        split_bf(v.z, h2, l2); split_bf(v.w, h3, l3);
        __nv_bfloat162 p;
        p.x = h0; p.y = h1; *(__nv_bfloat162*)&H[(size_t)i * 4]     = p;
        p.x = h2; p.y = h3; *(__nv_bfloat162*)&H[(size_t)i * 4 + 2] = p;
        p.x = l0; p.y = l1; *(__nv_bfloat162*)&L[(size_t)i * 4]     = p;
        p.x = l2; p.y = l3; *(__nv_bfloat162*)&L[(size_t)i * 4 + 2] = p;
    }
}

// ---------------- gates: one WARP per token ----------------
__global__ void gates_kernel(const float* __restrict__ x,
                             const float* __restrict__ bias_pre,
                             const float* __restrict__ bias_post,
                             const float* __restrict__ bias_res,
                             const float* __restrict__ alpha_pre,
                             const float* __restrict__ alpha_post,
                             const float* __restrict__ alpha_res) {
    int t = (blockIdx.x * blockDim.x + threadIdx.x) >> 5;   // token id
    int lane = threadIdx.x & 31;
    const float* xr = x + (size_t)t * C_DIM;

    float vals[25];
    #pragma unroll
    for (int j = 0; j < 25; j++) vals[j] = 0.f;

    #pragma unroll 4
    for (int i = 0; i < C_DIM / 32; i++) {
        int c = i * 32 + lane;
        float xv = xr[c];
        vals[24] += xv * xv;
        const float* w = &g_Weff[c * NDC];
        #pragma unroll
        for (int j = 0; j < NDC; j++) vals[j] += xv * w[j];
    }
    #pragma unroll
    for (int o = 16; o; o >>= 1)
        #pragma unroll
        for (int j = 0; j < 25; j++)
            vals[j] += __shfl_down_sync(0xffffffffu, vals[j], o);

    float spre = 0.f;
    if (lane == 0) {
        float rms = sqrtf(vals[24] * (1.f / (float)C_DIM) + 1e-8f);
        float inv = 1.f / rms;
        float dyn[NDC];
        #pragma unroll
        for (int j = 0; j < NDC; j++) dyn[j] = vals[j] * inv;

        float ap = alpha_pre[0], apo = alpha_post[0], ar = alpha_res[0];
        #pragma unroll
        for (int s = 0; s < NSTR; s++)
            spre += 1.f / (1.f + expf(-(ap * dyn[s] + bias_pre[s])));
        float hp[NSTR];
        #pragma unroll
        for (int s = 0; s < NSTR; s++)
            hp[s] = 2.f / (1.f + expf(-(apo * dyn[NSTR + s] + bias_post[s])));

        float M[NSTR][NSTR];
        #pragma unroll
        for (int i = 0; i < NSTR; i++)
            #pragma unroll
            for (int j = 0; j < NSTR; j++)
                M[i][j] = expf(ar * dyn[2 * NSTR + i * NSTR + j] + bias_res[i * NSTR + j]);
        for (int it = 0; it < 20; it++) {
            float cs[NSTR];
            #pragma unroll
            for (int j = 0; j < NSTR; j++) {
                cs[j] = 0.f;
                #pragma unroll
                for (int i = 0; i < NSTR; i++) cs[j] += M[i][j];
                cs[j] = 1.f / (cs[j] + 1e-8f);
            }
            #pragma unroll
            for (int i = 0; i < NSTR; i++) {
                float rs = 0.f;
                #pragma unroll
                for (int j = 0; j < NSTR; j++) { M[i][j] *= cs[j]; rs += M[i][j]; }
                rs = 1.f / (rs + 1e-8f);
                #pragma unroll
                for (int j = 0; j < NSTR; j++) M[i][j] *= rs;
            }
        }
        #pragma unroll
        for (int s = 0; s < NSTR; s++) {
            float rsum = 0.f;
            #pragma unroll
            for (int j = 0; j < NSTR; j++) rsum += M[s][j];
            g_hpost[t * NSTR + s] = hp[s];
            g_rsum[t * NSTR + s] = rsum;
        }
    }
    spre = __shfl_sync(0xffffffffu, spre, 0);

    #pragma unroll 4
    for (int i = 0; i < C_DIM / 32; i++) {
        int c = i * 32 + lane;
        float v = spre * xr[c];
        __nv_bfloat16 h, l;
        split_bf(v, h, l);
        g_premixH[(size_t)t * C_DIM + c] = h;
        g_premixL[(size_t)t * C_DIM + c] = l;
    }
}

// ---------------- bf16x3 tensor-core GEMM, 4-stage cp.async ----------------
#define BM 128
#define BN 128
#define BK 16
#define STAGES 4
// per-stage byte offsets within dynamic smem
#define AH_OFF 0
#define AL_OFF 6144          // 128*24*2
#define BH_OFF 12288
#define BL_OFF 16640         // +16*136*2
#define SSTRIDE 20992
#define SMEM_TOTAL (STAGES * SSTRIDE)   // 83968

__device__ __forceinline__ void load_stage(
    uint32_t st, int tid,
    const __nv_bfloat16* __restrict__ AH, const __nv_bfloat16* __restrict__ AL,
    const __nv_bfloat16* __restrict__ BH, const __nv_bfloat16* __restrict__ BL,
    int bm, int bn, int K, int N, int kt) {
    int r = tid >> 1, c8 = (tid & 1) * 8;
    size_t aoff = (size_t)(bm + r) * K + kt * BK + c8;
    CP16(st + AH_OFF + r * 48 + c8 * 2, AH + aoff);
    CP16(st + AL_OFF + r * 48 + c8 * 2, AL + aoff);
    int rb = tid >> 4, cb8 = (tid & 15) * 8;
    size_t boff = (size_t)(kt * BK + rb) * N + bn + cb8;
    CP16(st + BH_OFF + rb * 272 + cb8 * 2, BH + boff);
    CP16(st + BL_OFF + rb * 272 + cb8 * 2, BL + boff);
}

// EPI 0: gelu -> CH/CL (stride N). EPI 2: fused merge -> CH/CL (stride HID).
// EPI 3: +bias +resid -> fp32 outF.
template <int EPI>
__global__ void __launch_bounds__(256, 2) mma_gemm(
    const __nv_bfloat16* __restrict__ AH, const __nv_bfloat16* __restrict__ AL,
    const __nv_bfloat16* __restrict__ BH, const __nv_bfloat16* __restrict__ BL,
    const float* __restrict__ bias, const float* __restrict__ xin,
    __nv_bfloat16* __restrict__ CH, __nv_bfloat16* __restrict__ CL,
    float* __restrict__ outF, int M, int N, int K) {
    extern __shared__ char smem[];
    uint32_t sb = sa(smem);
    int tid = threadIdx.x;
    int lane = tid & 31;
    int wid = tid >> 5;
    int wm = wid & 1;
    int wn = wid >> 1;
    int bm = blockIdx.y * BM, bn = blockIdx.x * BN;
    int KT = K / BK;

    // prologue: stages 0..2
    #pragma unroll
    for (int s = 0; s < STAGES - 1; s++) {
        load_stage(sb + s * SSTRIDE, tid, AH, AL, BH, BL, bm, bn, K, N, s);
        CP_COMMIT();
    }

    float acc[4][4][4];
    #pragma unroll
    for (int i = 0; i < 4; i++)
        #pragma unroll
        for (int j = 0; j < 4; j++)
            #pragma unroll
            for (int q = 0; q < 4; q++) acc[i][j][q] = 0.f;

    int a_m = wm * 64 + (lane & 15);
    int a_k = (lane >> 4) * 8;
    int b_k = ((lane >> 3) & 1) * 8 + (lane & 7);
    int b_n0 = wn * 32 + (lane >> 4) * 8;

    for (int kt = 0; kt < KT; kt++) {
        CP_WAIT2();
        __syncthreads();
        if (kt + STAGES - 1 < KT)
            load_stage(sb + ((kt + STAGES - 1) & (STAGES - 1)) * SSTRIDE, tid,
                       AH, AL, BH, BL, bm, bn, K, N, kt + STAGES - 1);
        CP_COMMIT();

        uint32_t st = sb + (kt & (STAGES - 1)) * SSTRIDE;

        uint32_t aH[4][4], aL[4][4], bH[4][2], bL[4][2];
        #pragma unroll
        for (int mt = 0; mt < 4; mt++) {
            uint32_t arow = st + (a_m + mt * 16) * 48 + a_k * 2;
            ldsm4(aH[mt], arow + AH_OFF);
            ldsm4(aL[mt], arow + AL_OFF);
        }
        #pragma unroll
        for (int nr = 0; nr < 2; nr++) {
            uint32_t baddr = st + b_k * 272 + (b_n0 + nr * 16) * 2;
            uint32_t r[4];
            ldsm4t(r, baddr + BH_OFF);
            bH[nr * 2][0] = r[0]; bH[nr * 2][1] = r[1];
            bH[nr * 2 + 1][0] = r[2]; bH[nr * 2 + 1][1] = r[3];
            ldsm4t(r, baddr + BL_OFF);
            bL[nr * 2][0] = r[0]; bL[nr * 2][1] = r[1];
            bL[nr * 2 + 1][0] = r[2]; bL[nr * 2 + 1][1] = r[3];
        }

        #pragma unroll
        for (int mt = 0; mt < 4; mt++)
            #pragma unroll
            for (int nt = 0; nt < 4; nt++) {
                mma_bf16(acc[mt][nt], aH[mt], bH[nt]);
                mma_bf16(acc[mt][nt], aH[mt], bL[nt]);
                mma_bf16(acc[mt][nt], aL[mt], bH[nt]);
            }
    }

    // -------- epilogue --------
    int g = lane >> 2, tg = lane & 3;
    #pragma unroll
    for (int mt = 0; mt < 4; mt++) {
        #pragma unroll
        for (int half = 0; half < 2; half++) {
            int row = bm + wm * 64 + mt * 16 + g + half * 8;
            float rs[NSTR], hp[NSTR];
            if (EPI == 2) {
                float4 r4 = *(const float4*)&g_rsum[row * NSTR];
                float4 h4 = *(const float4*)&g_hpost[row * NSTR];
                rs[0] = r4.x; rs[1] = r4.y; rs[2] = r4.z; rs[3] = r4.w;
                hp[0] = h4.x; hp[1] = h4.y; hp[2] = h4.z; hp[3] = h4.w;
            }
            #pragma unroll
            for (int nt = 0; nt < 4; nt++) {
                int col = bn + wn * 32 + nt * 8 + tg * 2;
                float2 bv = *(const float2*)&bias[col];
                float v0 = acc[mt][nt][half * 2 + 0] + bv.x;
                float v1 = acc[mt][nt][half * 2 + 1] + bv.y;
                if (EPI == 0) {
                    v0 = gelu_exact(v0);
                    v1 = gelu_exact(v1);
                    __nv_bfloat16 h0, l0, h1, l1;
                    split_bf(v0, h0, l0);
                    split_bf(v1, h1, l1);
                    size_t off = (size_t)row * N + col;
                    __nv_bfloat162 p;
                    p.x = h0; p.y = h1; *(__nv_bfloat162*)&CH[off] = p;
                    p.x = l0; p.y = l1; *(__nv_bfloat162*)&CL[off] = p;
                } else if (EPI == 2) {
                    float2 xv = *(const float2*)&xin[(size_t)row * N + col];
                    #pragma unroll
                    for (int s = 0; s < NSTR; s++) {
                        float m0 = rs[s] * xv.x + hp[s] * v0;
                        float m1 = rs[s] * xv.y + hp[s] * v1;
                        __nv_bfloat16 h0, l0, h1, l1;
                        split_bf(m0, h0, l0);
                        split_bf(m1, h1, l1);
                        size_t off = (size_t)row * HID + s * C_DIM + col;
                        __nv_bfloat162 p;
                        p.x = h0; p.y = h1; *(__nv_bfloat162*)&CH[off] = p;
                        p.x = l0; p.y = l1; *(__nv_bfloat162*)&CL[off] = p;
                    }
                } else {
                    float2 xv = *(const float2*)&xin[(size_t)row * N + col];
                    float2 o;
                    o.x = v0 + xv.x;
                    o.y = v1 + xv.y;
                    *(float2*)&outF[(size_t)row * N + col] = o;
                }
            }
        }
    }
}

// ---------------- launch ----------------
extern "C" void kernel_launch(void* const* d_in, const int* in_sizes, int n_in,
                              void* d_out, int out_size) {
    const float* x         = (const float*)d_in[0];
    const float* rms_w     = (const float*)d_in[1];
    const float* W_dyn     = (const float*)d_in[2];
    const float* bias_pre  = (const float*)d_in[3];
    const float* bias_post = (const float*)d_in[4];
    const float* bias_res  = (const float*)d_in[5];
    const float* alpha_pre = (const float*)d_in[6];
    const float* alpha_post= (const float*)d_in[7];
    const float* alpha_res = (const float*)d_in[8];
    const float* W1        = (const float*)d_in[9];
    const float* b1        = (const float*)d_in[10];
    const float* W2        = (const float*)d_in[11];
    const float* b2        = (const float*)d_in[12];
    const float* Wout      = (const float*)d_in[13];
    const float* bout      = (const float*)d_in[14];
    float* out = (float*)d_out;

    int T = in_sizes[0] / C_DIM;   // 8192

    __nv_bfloat16 *premixH, *premixL, *hH, *hL, *mergedH, *mergedL;
    __nv_bfloat16 *w1H, *w1L, *w2H, *w2L, *woH, *woL;
    cudaGetSymbolAddress((void**)&premixH, g_premixH);
    cudaGetSymbolAddress((void**)&premixL, g_premixL);
    cudaGetSymbolAddress((void**)&hH, g_hH);
    cudaGetSymbolAddress((void**)&hL, g_hL);
    cudaGetSymbolAddress((void**)&mergedH, g_mergedH);
    cudaGetSymbolAddress((void**)&mergedL, g_mergedL);
    cudaGetSymbolAddress((void**)&w1H, g_W1H);
    cudaGetSymbolAddress((void**)&w1L, g_W1L);
    cudaGetSymbolAddress((void**)&w2H, g_W2H);
    cudaGetSymbolAddress((void**)&w2L, g_W2L);
    cudaGetSymbolAddress((void**)&woH, g_WoH);
    cudaGetSymbolAddress((void**)&woL, g_WoL);

    cudaFuncSetAttribute(mma_gemm<0>, cudaFuncAttributeMaxDynamicSharedMemorySize, SMEM_TOTAL);
    cudaFuncSetAttribute(mma_gemm<2>, cudaFuncAttributeMaxDynamicSharedMemorySize, SMEM_TOTAL);
    cudaFuncSetAttribute(mma_gemm<3>, cudaFuncAttributeMaxDynamicSharedMemorySize, SMEM_TOTAL);

    // 1. prep
    weff_kernel<<<(C_DIM * NDC + 255) / 256, 256>>>(rms_w, W_dyn);
    int wn4 = C_DIM * HID / 4;
    split_kernel<<<2048, 256>>>(W1, w1H, w1L, wn4);
    split_kernel<<<2048, 256>>>(W2, w2H, w2L, wn4);
    split_kernel<<<2048, 256>>>(Wout, woH, woL, wn4);
    // 2. gates + sinkhorn + premix (warp per token)
    gates_kernel<<<T / 8, 256>>>(x, bias_pre, bias_post, bias_res,
                                 alpha_pre, alpha_post, alpha_res);
    // 3. h = gelu(premix @ W1 + b1)
    mma_gemm<0><<<dim3(HID / BN, T / BM), 256, SMEM_TOTAL>>>(
        premixH, premixL, w1H, w1L, b1, nullptr, hH, hL, nullptr, T, HID, C_DIM);
    // 4. fout = h @ W2 + b2, fused merge -> mergedH/L
    mma_gemm<2><<<dim3(C_DIM / BN, T / BM), 256, SMEM_TOTAL>>>(
        hH, hL, w2H, w2L, b2, x, mergedH, mergedL, nullptr, T, C_DIM, HID);
    // 5. out = merged @ Wout + bout + x
    mma_gemm<3><<<dim3(C_DIM / BN, T / BM), 256, SMEM_TOTAL>>>(
        mergedH, mergedL, woH, woL, bout, x, nullptr, nullptr, out, T, C_DIM, HID);
}

// round 7
// speedup vs baseline: 6.0530x; 2.2615x over previous
#include <cuda_runtime.h>
#include <cuda_fp16.h>
#include <math.h>
#include <stdint.h>

#define C_DIM 1024
#define NSTR 4
#define HID 4096
#define NDC 24
#define T_MAX 8192

// ---------------- scratch ----------------
__device__ float g_Weff[C_DIM * NDC];
__device__ float g_hpost[T_MAX * NSTR];
__device__ float g_rsum[T_MAX * NSTR];

__device__ __half g_premix[(size_t)T_MAX * C_DIM];
__device__ __half g_h[(size_t)T_MAX * HID];
__device__ __half g_merged[(size_t)T_MAX * HID];
__device__ __half g_W1h[(size_t)C_DIM * HID];
__device__ __half g_W2h[(size_t)HID * C_DIM];
__device__ __half g_Woh[(size_t)HID * C_DIM];

// ---------------- helpers ----------------
__device__ __forceinline__ uint32_t sa(const void* p) {
    return (uint32_t)__cvta_generic_to_shared(p);
}
__device__ __forceinline__ void ldsm4(uint32_t* r, uint32_t addr) {
    asm volatile("ldmatrix.sync.aligned.m8n8.x4.shared.b16 {%0,%1,%2,%3},[%4];"
                 : "=r"(r[0]), "=r"(r[1]), "=r"(r[2]), "=r"(r[3]) : "r"(addr));
}
__device__ __forceinline__ void ldsm4t(uint32_t* r, uint32_t addr) {
    asm volatile("ldmatrix.sync.aligned.m8n8.x4.trans.shared.b16 {%0,%1,%2,%3},[%4];"
                 : "=r"(r[0]), "=r"(r[1]), "=r"(r[2]), "=r"(r[3]) : "r"(addr));
}
__device__ __forceinline__ void mma_f16(float* c, const uint32_t* a, const uint32_t* b) {
    asm volatile(
        "mma.sync.aligned.m16n8k16.row.col.f32.f16.f16.f32 "
        "{%0,%1,%2,%3},{%4,%5,%6,%7},{%8,%9},{%0,%1,%2,%3};"
        : "+f"(c[0]), "+f"(c[1]), "+f"(c[2]), "+f"(c[3])
        : "r"(a[0]), "r"(a[1]), "r"(a[2]), "r"(a[3]), "r"(b[0]), "r"(b[1]));
}
__device__ __forceinline__ float gelu_exact(float v) {
    return 0.5f * v * (1.f + erff(v * 0.70710678118654752f));
}
#define CP16(dst, src) \
    asm volatile("cp.async.cg.shared.global [%0], [%1], 16;" :: "r"(dst), "l"(src))
#define CP_COMMIT() asm volatile("cp.async.commit_group;" ::: "memory")
#define CP_WAIT2() asm volatile("cp.async.wait_group 2;" ::: "memory")

// ---------------- Weff precompute ----------------
__global__ void weff_kernel(const float* __restrict__ rmsw, const float* __restrict__ Wdyn) {
    int idx = blockIdx.x * blockDim.x + threadIdx.x;
    if (idx >= C_DIM * NDC) return;
    int c = idx / NDC, j = idx % NDC;
    float s = 0.f;
    #pragma unroll
    for (int st = 0; st < NSTR; st++) {
        int k = st * C_DIM + c;
        s += rmsw[k] * Wdyn[(size_t)k * NDC + j];
    }
    g_Weff[idx] = s;
}

// ---------------- fp32 -> fp16 convert ----------------
__global__ void cvt_kernel(const float* __restrict__ W, __half* __restrict__ H, int n4) {
    for (int i = blockIdx.x * blockDim.x + threadIdx.x; i < n4; i += gridDim.x * blockDim.x) {
        float4 v = *(const float4*)&W[(size_t)i * 4];
        __half2 p0 = __float22half2_rn(make_float2(v.x, v.y));
        __half2 p1 = __float22half2_rn(make_float2(v.z, v.w));
        *(__half2*)&H[(size_t)i * 4]     = p0;
        *(__half2*)&H[(size_t)i * 4 + 2] = p1;
    }
}

// ---------------- gates: one WARP per token ----------------
__global__ void gates_kernel(const float* __restrict__ x,
                             const float* __restrict__ bias_pre,
                             const float* __restrict__ bias_post,
                             const float* __restrict__ bias_res,
                             const float* __restrict__ alpha_pre,
                             const float* __restrict__ alpha_post,
                             const float* __restrict__ alpha_res) {
    int t = (blockIdx.x * blockDim.x + threadIdx.x) >> 5;
    int lane = threadIdx.x & 31;
    const float* xr = x + (size_t)t * C_DIM;

    float vals[25];
    #pragma unroll
    for (int j = 0; j < 25; j++) vals[j] = 0.f;

    #pragma unroll 4
    for (int i = 0; i < C_DIM / 32; i++) {
        int c = i * 32 + lane;
        float xv = xr[c];
        vals[24] += xv * xv;
        const float* w = &g_Weff[c * NDC];
        #pragma unroll
        for (int j = 0; j < NDC; j++) vals[j] += xv * w[j];
    }
    #pragma unroll
    for (int o = 16; o; o >>= 1)
        #pragma unroll
        for (int j = 0; j < 25; j++)
            vals[j] += __shfl_down_sync(0xffffffffu, vals[j], o);

    float spre = 0.f;
    if (lane == 0) {
        float rms = sqrtf(vals[24] * (1.f / (float)C_DIM) + 1e-8f);
        float inv = 1.f / rms;
        float dyn[NDC];
        #pragma unroll
        for (int j = 0; j < NDC; j++) dyn[j] = vals[j] * inv;

        float ap = alpha_pre[0], apo = alpha_post[0], ar = alpha_res[0];
        #pragma unroll
        for (int s = 0; s < NSTR; s++)
            spre += 1.f / (1.f + expf(-(ap * dyn[s] + bias_pre[s])));
        float hp[NSTR];
        #pragma unroll
        for (int s = 0; s < NSTR; s++)
            hp[s] = 2.f / (1.f + expf(-(apo * dyn[NSTR + s] + bias_post[s])));

        float M[NSTR][NSTR];
        #pragma unroll
        for (int i = 0; i < NSTR; i++)
            #pragma unroll
            for (int j = 0; j < NSTR; j++)
                M[i][j] = expf(ar * dyn[2 * NSTR + i * NSTR + j] + bias_res[i * NSTR + j]);
        for (int it = 0; it < 20; it++) {
            float cs[NSTR];
            #pragma unroll
            for (int j = 0; j < NSTR; j++) {
                cs[j] = 0.f;
                #pragma unroll
                for (int i = 0; i < NSTR; i++) cs[j] += M[i][j];
                cs[j] = 1.f / (cs[j] + 1e-8f);
            }
            #pragma unroll
            for (int i = 0; i < NSTR; i++) {
                float rs = 0.f;
                #pragma unroll
                for (int j = 0; j < NSTR; j++) { M[i][j] *= cs[j]; rs += M[i][j]; }
                rs = 1.f / (rs + 1e-8f);
                #pragma unroll
                for (int j = 0; j < NSTR; j++) M[i][j] *= rs;
            }
        }
        #pragma unroll
        for (int s = 0; s < NSTR; s++) {
            float rsum = 0.f;
            #pragma unroll
            for (int j = 0; j < NSTR; j++) rsum += M[s][j];
            g_hpost[t * NSTR + s] = hp[s];
            g_rsum[t * NSTR + s] = rsum;
        }
    }
    spre = __shfl_sync(0xffffffffu, spre, 0);

    #pragma unroll 4
    for (int i = 0; i < C_DIM / 32; i++) {
        int c = i * 32 + lane;
        g_premix[(size_t)t * C_DIM + c] = __float2half(spre * xr[c]);
    }
}

// ---------------- fp16 tensor-core GEMM, 4-stage cp.async ----------------
#define BM 128
#define BN 128
#define BK 16
#define STAGES 4
#define A_OFF 0
#define B_OFF 6144            // 128 rows * 48B pitch
#define SSTRIDE 10496         // + 16 * 272B
#define SMEM_TOTAL (STAGES * SSTRIDE)   // 41984

__device__ __forceinline__ void load_stage(
    uint32_t st, int tid,
    const __half* __restrict__ A, const __half* __restrict__ B,
    int bm, int bn, int K, int N, int kt) {
    int r = tid >> 1, c8 = (tid & 1) * 8;
    CP16(st + A_OFF + r * 48 + c8 * 2, A + (size_t)(bm + r) * K + kt * BK + c8);
    int rb = tid >> 4, cb8 = (tid & 15) * 8;
    CP16(st + B_OFF + rb * 272 + cb8 * 2, B + (size_t)(kt * BK + rb) * N + bn + cb8);
}

// EPI 0: gelu -> Ch fp16 (stride N). EPI 2: fused merge -> Ch fp16 (stride HID).
// EPI 3: +bias +resid -> fp32 outF.
template <int EPI>
__global__ void __launch_bounds__(256, 2) mma_gemm(
    const __half* __restrict__ A, const __half* __restrict__ B,
    const float* __restrict__ bias, const float* __restrict__ xin,
    __half* __restrict__ Ch, float* __restrict__ outF, int M, int N, int K) {
    extern __shared__ char smem[];
    uint32_t sb = sa(smem);
    int tid = threadIdx.x;
    int lane = tid & 31;
    int wid = tid >> 5;
    int wm = wid & 1;
    int wn = wid >> 1;
    int bm = blockIdx.y * BM, bn = blockIdx.x * BN;
    int KT = K / BK;

    #pragma unroll
    for (int s = 0; s < STAGES - 1; s++) {
        load_stage(sb + s * SSTRIDE, tid, A, B, bm, bn, K, N, s);
        CP_COMMIT();
    }

    float acc[4][4][4];
    #pragma unroll
    for (int i = 0; i < 4; i++)
        #pragma unroll
        for (int j = 0; j < 4; j++)
            #pragma unroll
            for (int q = 0; q < 4; q++) acc[i][j][q] = 0.f;

    int a_m = wm * 64 + (lane & 15);
    int a_k = (lane >> 4) * 8;
    int b_k = ((lane >> 3) & 1) * 8 + (lane & 7);
    int b_n0 = wn * 32 + (lane >> 4) * 8;

    #pragma unroll 2
    for (int kt = 0; kt < KT; kt++) {
        CP_WAIT2();
        __syncthreads();
        if (kt + STAGES - 1 < KT)
            load_stage(sb + ((kt + STAGES - 1) & (STAGES - 1)) * SSTRIDE, tid,
                       A, B, bm, bn, K, N, kt + STAGES - 1);
        CP_COMMIT();

        uint32_t st = sb + (kt & (STAGES - 1)) * SSTRIDE;

        uint32_t a[4][4], b[4][2];
        #pragma unroll
        for (int mt = 0; mt < 4; mt++)
            ldsm4(a[mt], st + A_OFF + (a_m + mt * 16) * 48 + a_k * 2);
        #pragma unroll
        for (int nr = 0; nr < 2; nr++) {
            uint32_t r[4];
            ldsm4t(r, st + B_OFF + b_k * 272 + (b_n0 + nr * 16) * 2);
            b[nr * 2][0] = r[0]; b[nr * 2][1] = r[1];
            b[nr * 2 + 1][0] = r[2]; b[nr * 2 + 1][1] = r[3];
        }

        #pragma unroll
        for (int mt = 0; mt < 4; mt++)
            #pragma unroll
            for (int nt = 0; nt < 4; nt++)
                mma_f16(acc[mt][nt], a[mt], b[nt]);
    }

    // -------- epilogue --------
    int g = lane >> 2, tg = lane & 3;
    #pragma unroll
    for (int mt = 0; mt < 4; mt++) {
        #pragma unroll
        for (int half_ = 0; half_ < 2; half_++) {
            int row = bm + wm * 64 + mt * 16 + g + half_ * 8;
            float rs[NSTR], hp[NSTR];
            if (EPI == 2) {
                float4 r4 = *(const float4*)&g_rsum[row * NSTR];
                float4 h4 = *(const float4*)&g_hpost[row * NSTR];
                rs[0] = r4.x; rs[1] = r4.y; rs[2] = r4.z; rs[3] = r4.w;
                hp[0] = h4.x; hp[1] = h4.y; hp[2] = h4.z; hp[3] = h4.w;
            }
            #pragma unroll
            for (int nt = 0; nt < 4; nt++) {
                int col = bn + wn * 32 + nt * 8 + tg * 2;
                float2 bv = *(const float2*)&bias[col];
                float v0 = acc[mt][nt][half_ * 2 + 0] + bv.x;
                float v1 = acc[mt][nt][half_ * 2 + 1] + bv.y;
                if (EPI == 0) {
                    v0 = gelu_exact(v0);
                    v1 = gelu_exact(v1);
                    *(__half2*)&Ch[(size_t)row * N + col] =
                        __float22half2_rn(make_float2(v0, v1));
                } else if (EPI == 2) {
                    float2 xv = *(const float2*)&xin[(size_t)row * N + col];
                    #pragma unroll
                    for (int s = 0; s < NSTR; s++) {
                        float m0 = rs[s] * xv.x + hp[s] * v0;
                        float m1 = rs[s] * xv.y + hp[s] * v1;
                        *(__half2*)&Ch[(size_t)row * HID + s * C_DIM + col] =
                            __float22half2_rn(make_float2(m0, m1));
                    }
                } else {
                    float2 xv = *(const float2*)&xin[(size_t)row * N + col];
                    float2 o;
                    o.x = v0 + xv.x;
                    o.y = v1 + xv.y;
                    *(float2*)&outF[(size_t)row * N + col] = o;
                }
            }
        }
    }
}

// ---------------- launch ----------------
extern "C" void kernel_launch(void* const* d_in, const int* in_sizes, int n_in,
                              void* d_out, int out_size) {
    const float* x         = (const float*)d_in[0];
    const float* rms_w     = (const float*)d_in[1];
    const float* W_dyn     = (const float*)d_in[2];
    const float* bias_pre  = (const float*)d_in[3];
    const float* bias_post = (const float*)d_in[4];
    const float* bias_res  = (const float*)d_in[5];
    const float* alpha_pre = (const float*)d_in[6];
    const float* alpha_post= (const float*)d_in[7];
    const float* alpha_res = (const float*)d_in[8];
    const float* W1        = (const float*)d_in[9];
    const float* b1        = (const float*)d_in[10];
    const float* W2        = (const float*)d_in[11];
    const float* b2        = (const float*)d_in[12];
    const float* Wout      = (const float*)d_in[13];
    const float* bout      = (const float*)d_in[14];
    float* out = (float*)d_out;

    int T = in_sizes[0] / C_DIM;   // 8192

    __half *premix, *h, *merged, *w1h, *w2h, *woh;
    cudaGetSymbolAddress((void**)&premix, g_premix);
    cudaGetSymbolAddress((void**)&h, g_h);
    cudaGetSymbolAddress((void**)&merged, g_merged);
    cudaGetSymbolAddress((void**)&w1h, g_W1h);
    cudaGetSymbolAddress((void**)&w2h, g_W2h);
    cudaGetSymbolAddress((void**)&woh, g_Woh);

    cudaFuncSetAttribute(mma_gemm<0>, cudaFuncAttributeMaxDynamicSharedMemorySize, SMEM_TOTAL);
    cudaFuncSetAttribute(mma_gemm<2>, cudaFuncAttributeMaxDynamicSharedMemorySize, SMEM_TOTAL);
    cudaFuncSetAttribute(mma_gemm<3>, cudaFuncAttributeMaxDynamicSharedMemorySize, SMEM_TOTAL);

    // 1. prep
    weff_kernel<<<(C_DIM * NDC + 255) / 256, 256>>>(rms_w, W_dyn);
    int wn4 = C_DIM * HID / 4;
    cvt_kernel<<<2048, 256>>>(W1, w1h, wn4);
    cvt_kernel<<<2048, 256>>>(W2, w2h, wn4);
    cvt_kernel<<<2048, 256>>>(Wout, woh, wn4);
    // 2. gates + sinkhorn + premix (warp per token)
    gates_kernel<<<T / 8, 256>>>(x, bias_pre, bias_post, bias_res,
                                 alpha_pre, alpha_post, alpha_res);
    // 3. h = gelu(premix @ W1 + b1)
    mma_gemm<0><<<dim3(HID / BN, T / BM), 256, SMEM_TOTAL>>>(
        premix, w1h, b1, nullptr, h, nullptr, T, HID, C_DIM);
    // 4. fout = h @ W2 + b2, fused merge -> merged
    mma_gemm<2><<<dim3(C_DIM / BN, T / BM), 256, SMEM_TOTAL>>>(
        h, w2h, b2, x, merged, nullptr, T, C_DIM, HID);
    // 5. out = merged @ Wout + bout + x
    mma_gemm<3><<<dim3(C_DIM / BN, T / BM), 256, SMEM_TOTAL>>>(
        merged, woh, bout, x, nullptr, out, T, C_DIM, HID);
}

// round 8
// speedup vs baseline: 6.1354x; 1.0136x over previous
#include <cuda_runtime.h>
#include <cuda_fp16.h>
#include <math.h>
#include <stdint.h>

#define C_DIM 1024
#define NSTR 4
#define HID 4096
#define NDC 24
#define T_MAX 8192

// ---------------- scratch ----------------
__device__ float g_Weff[C_DIM * NDC];
__device__ float g_hpost[T_MAX * NSTR];
__device__ float g_rsum[T_MAX * NSTR];

__device__ __half g_premix[(size_t)T_MAX * C_DIM];
__device__ __half g_h[(size_t)T_MAX * HID];
__device__ __half g_merged[(size_t)T_MAX * HID];
__device__ __half g_W1h[(size_t)C_DIM * HID];
__device__ __half g_W2h[(size_t)HID * C_DIM];
__device__ __half g_Woh[(size_t)HID * C_DIM];

// ---------------- helpers ----------------
__device__ __forceinline__ uint32_t sa(const void* p) {
    return (uint32_t)__cvta_generic_to_shared(p);
}
__device__ __forceinline__ void ldsm4(uint32_t* r, uint32_t addr) {
    asm volatile("ldmatrix.sync.aligned.m8n8.x4.shared.b16 {%0,%1,%2,%3},[%4];"
                 : "=r"(r[0]), "=r"(r[1]), "=r"(r[2]), "=r"(r[3]) : "r"(addr));
}
__device__ __forceinline__ void ldsm4t(uint32_t* r, uint32_t addr) {
    asm volatile("ldmatrix.sync.aligned.m8n8.x4.trans.shared.b16 {%0,%1,%2,%3},[%4];"
                 : "=r"(r[0]), "=r"(r[1]), "=r"(r[2]), "=r"(r[3]) : "r"(addr));
}
__device__ __forceinline__ void mma_f16(float* c, const uint32_t* a, const uint32_t* b) {
    asm volatile(
        "mma.sync.aligned.m16n8k16.row.col.f32.f16.f16.f32 "
        "{%0,%1,%2,%3},{%4,%5,%6,%7},{%8,%9},{%0,%1,%2,%3};"
        : "+f"(c[0]), "+f"(c[1]), "+f"(c[2]), "+f"(c[3])
        : "r"(a[0]), "r"(a[1]), "r"(a[2]), "r"(a[3]), "r"(b[0]), "r"(b[1]));
}
__device__ __forceinline__ float gelu_exact(float v) {
    return 0.5f * v * (1.f + erff(v * 0.70710678118654752f));
}
#define CP16(dst, src) \
    asm volatile("cp.async.cg.shared.global [%0], [%1], 16;" :: "r"(dst), "l"(src))
#define CP_COMMIT() asm volatile("cp.async.commit_group;" ::: "memory")
#define CP_WAIT1() asm volatile("cp.async.wait_group 1;" ::: "memory")

// ---------------- Weff precompute ----------------
__global__ void weff_kernel(const float* __restrict__ rmsw, const float* __restrict__ Wdyn) {
    int idx = blockIdx.x * blockDim.x + threadIdx.x;
    if (idx >= C_DIM * NDC) return;
    int c = idx / NDC, j = idx % NDC;
    float s = 0.f;
    #pragma unroll
    for (int st = 0; st < NSTR; st++) {
        int k = st * C_DIM + c;
        s += rmsw[k] * Wdyn[(size_t)k * NDC + j];
    }
    g_Weff[idx] = s;
}

// ---------------- fp32 -> fp16 convert, all three weights in one launch ----------------
__global__ void cvt3_kernel(const float* __restrict__ W1, __half* __restrict__ H1,
                            const float* __restrict__ W2, __half* __restrict__ H2,
                            const float* __restrict__ W3, __half* __restrict__ H3,
                            int n4each) {
    int total = 3 * n4each;
    for (int i = blockIdx.x * blockDim.x + threadIdx.x; i < total; i += gridDim.x * blockDim.x) {
        int seg = i / n4each;
        int idx = i - seg * n4each;
        const float* W = (seg == 0) ? W1 : (seg == 1) ? W2 : W3;
        __half* H = (seg == 0) ? H1 : (seg == 1) ? H2 : H3;
        float4 v = *(const float4*)&W[(size_t)idx * 4];
        *(__half2*)&H[(size_t)idx * 4]     = __float22half2_rn(make_float2(v.x, v.y));
        *(__half2*)&H[(size_t)idx * 4 + 2] = __float22half2_rn(make_float2(v.z, v.w));
    }
}

// ---------------- gates: one WARP per token ----------------
__global__ void gates_kernel(const float* __restrict__ x,
                             const float* __restrict__ bias_pre,
                             const float* __restrict__ bias_post,
                             const float* __restrict__ bias_res,
                             const float* __restrict__ alpha_pre,
                             const float* __restrict__ alpha_post,
                             const float* __restrict__ alpha_res) {
    int t = (blockIdx.x * blockDim.x + threadIdx.x) >> 5;
    int lane = threadIdx.x & 31;
    const float* xr = x + (size_t)t * C_DIM;

    float vals[25];
    #pragma unroll
    for (int j = 0; j < 25; j++) vals[j] = 0.f;

    #pragma unroll 4
    for (int i = 0; i < C_DIM / 32; i++) {
        int c = i * 32 + lane;
        float xv = xr[c];
        vals[24] += xv * xv;
        const float* w = &g_Weff[c * NDC];
        #pragma unroll
        for (int j = 0; j < NDC; j++) vals[j] += xv * w[j];
    }
    #pragma unroll
    for (int o = 16; o; o >>= 1)
        #pragma unroll
        for (int j = 0; j < 25; j++)
            vals[j] += __shfl_down_sync(0xffffffffu, vals[j], o);

    float spre = 0.f;
    if (lane == 0) {
        float rms = sqrtf(vals[24] * (1.f / (float)C_DIM) + 1e-8f);
        float inv = 1.f / rms;
        float dyn[NDC];
        #pragma unroll
        for (int j = 0; j < NDC; j++) dyn[j] = vals[j] * inv;

        float ap = alpha_pre[0], apo = alpha_post[0], ar = alpha_res[0];
        #pragma unroll
        for (int s = 0; s < NSTR; s++)
            spre += 1.f / (1.f + expf(-(ap * dyn[s] + bias_pre[s])));
        float hp[NSTR];
        #pragma unroll
        for (int s = 0; s < NSTR; s++)
            hp[s] = 2.f / (1.f + expf(-(apo * dyn[NSTR + s] + bias_post[s])));

        float M[NSTR][NSTR];
        #pragma unroll
        for (int i = 0; i < NSTR; i++)
            #pragma unroll
            for (int j = 0; j < NSTR; j++)
                M[i][j] = expf(ar * dyn[2 * NSTR + i * NSTR + j] + bias_res[i * NSTR + j]);
        for (int it = 0; it < 20; it++) {
            float cs[NSTR];
            #pragma unroll
            for (int j = 0; j < NSTR; j++) {
                cs[j] = 0.f;
                #pragma unroll
                for (int i = 0; i < NSTR; i++) cs[j] += M[i][j];
                cs[j] = 1.f / (cs[j] + 1e-8f);
            }
            #pragma unroll
            for (int i = 0; i < NSTR; i++) {
                float rs = 0.f;
                #pragma unroll
                for (int j = 0; j < NSTR; j++) { M[i][j] *= cs[j]; rs += M[i][j]; }
                rs = 1.f / (rs + 1e-8f);
                #pragma unroll
                for (int j = 0; j < NSTR; j++) M[i][j] *= rs;
            }
        }
        #pragma unroll
        for (int s = 0; s < NSTR; s++) {
            float rsum = 0.f;
            #pragma unroll
            for (int j = 0; j < NSTR; j++) rsum += M[s][j];
            g_hpost[t * NSTR + s] = hp[s];
            g_rsum[t * NSTR + s] = rsum;
        }
    }
    spre = __shfl_sync(0xffffffffu, spre, 0);

    #pragma unroll 4
    for (int i = 0; i < C_DIM / 32; i++) {
        int c = i * 32 + lane;
        g_premix[(size_t)t * C_DIM + c] = __float2half(spre * xr[c]);
    }
}

// ---------------- fp16 tensor-core GEMM: BK=64, 3-stage cp.async ----------------
#define BM 128
#define BN 128
#define BK 64
#define STAGES 3
#define APITCH 144            // 64*2 + 16 pad (36 words == 4 mod 32: conflict-free ldsm)
#define BPITCH 272            // 128*2 + 16 pad
#define A_OFF 0
#define B_OFF (BM * APITCH)                  // 18432
#define SSTRIDE (B_OFF + BK * BPITCH)        // 18432 + 17408 = 35840
#define SMEM_TOTAL (STAGES * SSTRIDE)        // 107520

__device__ __forceinline__ void load_stage(
    uint32_t st, int tid,
    const __half* __restrict__ A, const __half* __restrict__ B,
    int bm, int bn, int K, int N, int kt) {
    // A: 128 rows x 64 cols = 1024 x 16B chunks; 4 per thread
    #pragma unroll
    for (int i = 0; i < 4; i++) {
        int q = tid + i * 256;
        int r = q >> 3, c8 = (q & 7) * 8;
        CP16(st + A_OFF + r * APITCH + c8 * 2, A + (size_t)(bm + r) * K + kt * BK + c8);
    }
    // B: 64 rows x 128 cols = 1024 x 16B chunks; 4 per thread
    #pragma unroll
    for (int i = 0; i < 4; i++) {
        int q = tid + i * 256;
        int r = q >> 4, c8 = (q & 15) * 8;
        CP16(st + B_OFF + r * BPITCH + c8 * 2, B + (size_t)(kt * BK + r) * N + bn + c8);
    }
}

// EPI 0: gelu -> Ch fp16 (stride N). EPI 2: fused merge -> Ch fp16 (stride HID).
// EPI 3: +bias +resid -> fp32 outF.
template <int EPI>
__global__ void __launch_bounds__(256, 2) mma_gemm(
    const __half* __restrict__ A, const __half* __restrict__ B,
    const float* __restrict__ bias, const float* __restrict__ xin,
    __half* __restrict__ Ch, float* __restrict__ outF, int M, int N, int K) {
    extern __shared__ char smem[];
    uint32_t sb = sa(smem);
    int tid = threadIdx.x;
    int lane = tid & 31;
    int wid = tid >> 5;
    int wm = wid & 1;
    int wn = wid >> 1;
    int bm = blockIdx.y * BM, bn = blockIdx.x * BN;
    int KT = K / BK;

    // prologue: stages 0,1
    load_stage(sb, tid, A, B, bm, bn, K, N, 0);
    CP_COMMIT();
    load_stage(sb + SSTRIDE, tid, A, B, bm, bn, K, N, 1);
    CP_COMMIT();

    float acc[4][4][4];
    #pragma unroll
    for (int i = 0; i < 4; i++)
        #pragma unroll
        for (int j = 0; j < 4; j++)
            #pragma unroll
            for (int q = 0; q < 4; q++) acc[i][j][q] = 0.f;

    int a_m = wm * 64 + (lane & 15);
    int a_k = (lane >> 4) * 8;
    int b_k = ((lane >> 3) & 1) * 8 + (lane & 7);
    int b_n0 = wn * 32 + (lane >> 4) * 8;

    int slot = 0, slot_ld = 2;
    for (int kt = 0; kt < KT; kt++) {
        CP_WAIT1();
        __syncthreads();
        if (kt + 2 < KT)
            load_stage(sb + slot_ld * SSTRIDE, tid, A, B, bm, bn, K, N, kt + 2);
        CP_COMMIT();

        uint32_t st = sb + slot * SSTRIDE;
        #pragma unroll
        for (int u = 0; u < BK / 16; u++) {
            uint32_t a[4][4], b[4][2];
            #pragma unroll
            for (int mt = 0; mt < 4; mt++)
                ldsm4(a[mt], st + A_OFF + (a_m + mt * 16) * APITCH + (u * 16 + a_k) * 2);
            #pragma unroll
            for (int nr = 0; nr < 2; nr++) {
                uint32_t r[4];
                ldsm4t(r, st + B_OFF + (u * 16 + b_k) * BPITCH + (b_n0 + nr * 16) * 2);
                b[nr * 2][0] = r[0]; b[nr * 2][1] = r[1];
                b[nr * 2 + 1][0] = r[2]; b[nr * 2 + 1][1] = r[3];
            }
            #pragma unroll
            for (int mt = 0; mt < 4; mt++)
                #pragma unroll
                for (int nt = 0; nt < 4; nt++)
                    mma_f16(acc[mt][nt], a[mt], b[nt]);
        }
        slot = (slot == STAGES - 1) ? 0 : slot + 1;
        slot_ld = (slot_ld == STAGES - 1) ? 0 : slot_ld + 1;
    }

    // -------- epilogue --------
    int g = lane >> 2, tg = lane & 3;
    #pragma unroll
    for (int mt = 0; mt < 4; mt++) {
        #pragma unroll
        for (int half_ = 0; half_ < 2; half_++) {
            int row = bm + wm * 64 + mt * 16 + g + half_ * 8;
            float rs[NSTR], hp[NSTR];
            if (EPI == 2) {
                float4 r4 = *(const float4*)&g_rsum[row * NSTR];
                float4 h4 = *(const float4*)&g_hpost[row * NSTR];
                rs[0] = r4.x; rs[1] = r4.y; rs[2] = r4.z; rs[3] = r4.w;
                hp[0] = h4.x; hp[1] = h4.y; hp[2] = h4.z; hp[3] = h4.w;
            }
            #pragma unroll
            for (int nt = 0; nt < 4; nt++) {
                int col = bn + wn * 32 + nt * 8 + tg * 2;
                float2 bv = *(const float2*)&bias[col];
                float v0 = acc[mt][nt][half_ * 2 + 0] + bv.x;
                float v1 = acc[mt][nt][half_ * 2 + 1] + bv.y;
                if (EPI == 0) {
                    v0 = gelu_exact(v0);
                    v1 = gelu_exact(v1);
                    *(__half2*)&Ch[(size_t)row * N + col] =
                        __float22half2_rn(make_float2(v0, v1));
                } else if (EPI == 2) {
                    float2 xv = *(const float2*)&xin[(size_t)row * N + col];
                    #pragma unroll
                    for (int s = 0; s < NSTR; s++) {
                        float m0 = rs[s] * xv.x + hp[s] * v0;
                        float m1 = rs[s] * xv.y + hp[s] * v1;
                        *(__half2*)&Ch[(size_t)row * HID + s * C_DIM + col] =
                            __float22half2_rn(make_float2(m0, m1));
                    }
                } else {
                    float2 xv = *(const float2*)&xin[(size_t)row * N + col];
                    float2 o;
                    o.x = v0 + xv.x;
                    o.y = v1 + xv.y;
                    *(float2*)&outF[(size_t)row * N + col] = o;
                }
            }
        }
    }
}

// ---------------- launch ----------------
extern "C" void kernel_launch(void* const* d_in, const int* in_sizes, int n_in,
                              void* d_out, int out_size) {
    const float* x         = (const float*)d_in[0];
    const float* rms_w     = (const float*)d_in[1];
    const float* W_dyn     = (const float*)d_in[2];
    const float* bias_pre  = (const float*)d_in[3];
    const float* bias_post = (const float*)d_in[4];
    const float* bias_res  = (const float*)d_in[5];
    const float* alpha_pre = (const float*)d_in[6];
    const float* alpha_post= (const float*)d_in[7];
    const float* alpha_res = (const float*)d_in[8];
    const float* W1        = (const float*)d_in[9];
    const float* b1        = (const float*)d_in[10];
    const float* W2        = (const float*)d_in[11];
    const float* b2        = (const float*)d_in[12];
    const float* Wout      = (const float*)d_in[13];
    const float* bout      = (const float*)d_in[14];
    float* out = (float*)d_out;

    int T = in_sizes[0] / C_DIM;   // 8192

    __half *premix, *h, *merged, *w1h, *w2h, *woh;
    cudaGetSymbolAddress((void**)&premix, g_premix);
    cudaGetSymbolAddress((void**)&h, g_h);
    cudaGetSymbolAddress((void**)&merged, g_merged);
    cudaGetSymbolAddress((void**)&w1h, g_W1h);
    cudaGetSymbolAddress((void**)&w2h, g_W2h);
    cudaGetSymbolAddress((void**)&woh, g_Woh);

    cudaFuncSetAttribute(mma_gemm<0>, cudaFuncAttributeMaxDynamicSharedMemorySize, SMEM_TOTAL);
    cudaFuncSetAttribute(mma_gemm<2>, cudaFuncAttributeMaxDynamicSharedMemorySize, SMEM_TOTAL);
    cudaFuncSetAttribute(mma_gemm<3>, cudaFuncAttributeMaxDynamicSharedMemorySize, SMEM_TOTAL);

    // 1. prep
    weff_kernel<<<(C_DIM * NDC + 255) / 256, 256>>>(rms_w, W_dyn);
    cvt3_kernel<<<3072, 256>>>(W1, w1h, W2, w2h, Wout, woh, C_DIM * HID / 4);
    // 2. gates + sinkhorn + premix (warp per token)
    gates_kernel<<<T / 8, 256>>>(x, bias_pre, bias_post, bias_res,
                                 alpha_pre, alpha_post, alpha_res);
    // 3. h = gelu(premix @ W1 + b1)
    mma_gemm<0><<<dim3(HID / BN, T / BM), 256, SMEM_TOTAL>>>(
        premix, w1h, b1, nullptr, h, nullptr, T, HID, C_DIM);
    // 4. fout = h @ W2 + b2, fused merge -> merged
    mma_gemm<2><<<dim3(C_DIM / BN, T / BM), 256, SMEM_TOTAL>>>(
        h, w2h, b2, x, merged, nullptr, T, C_DIM, HID);
    // 5. out = merged @ Wout + bout + x
    mma_gemm<3><<<dim3(C_DIM / BN, T / BM), 256, SMEM_TOTAL>>>(
        merged, woh, bout, x, nullptr, out, T, C_DIM, HID);
}